// round 1
// baseline (speedup 1.0000x reference)
#include <cuda_runtime.h>

#define Nn 64
#define Cc 128
#define Ff 2048

// Scratch: softmax weights W[n][c][m]  (64*128*128 floats = 4 MB)
__device__ float g_W[Nn * Cc * Cc];

// ---------------------------------------------------------------------------
// Kernel 1: for fixed c, compute S[n][m] = sum_f X[n,c,f] * A[c,m,f]
// (64x128 tile, K=2048), then softmax over m, write W[n][c][m].
// Grid: 128 blocks (one per c), 256 threads.
// ---------------------------------------------------------------------------
__global__ __launch_bounds__(256) void k_scores(const float* __restrict__ X,
                                                const float* __restrict__ A) {
    const int c   = blockIdx.x;
    const int tid = threadIdx.x;

    // smem: Xs[32][68] (2176) + As[32][132] (4224)  -> reused as S[64][132] (8448)
    __shared__ float smem[64 * 132];
    float* Xs = smem;             // [k][n], stride 68
    float* As = smem + 32 * 68;   // [k][m], stride 132

    const int tm = tid & 15;
    const int tn = tid >> 4;
    const int n0 = tn * 4;
    const int m0 = tm * 8;

    float acc[4][8];
#pragma unroll
    for (int i = 0; i < 4; i++)
#pragma unroll
        for (int j = 0; j < 8; j++) acc[i][j] = 0.0f;

    const float* Xbase = X + (size_t)c * Ff;          // X[(n*Cc + c)*Ff + f]
    const float* Abase = A + (size_t)c * Cc * Ff;     // A[(c*Cc + m)*Ff + f]

    for (int f0 = 0; f0 < Ff; f0 += 32) {
        // load X chunk: 64(n) x 32(k) = 512 float4, 2 per thread
#pragma unroll
        for (int i = 0; i < 2; i++) {
            int v  = tid + i * 256;
            int n  = v >> 3;
            int k4 = (v & 7) * 4;
            float4 x = *(const float4*)&Xbase[((size_t)n * Cc) * Ff + f0 + k4];
            Xs[(k4 + 0) * 68 + n] = x.x;
            Xs[(k4 + 1) * 68 + n] = x.y;
            Xs[(k4 + 2) * 68 + n] = x.z;
            Xs[(k4 + 3) * 68 + n] = x.w;
        }
        // load A chunk: 128(m) x 32(k) = 1024 float4, 4 per thread
#pragma unroll
        for (int i = 0; i < 4; i++) {
            int v  = tid + i * 256;
            int m  = v >> 3;
            int k4 = (v & 7) * 4;
            float4 a = *(const float4*)&Abase[(size_t)m * Ff + f0 + k4];
            As[(k4 + 0) * 132 + m] = a.x;
            As[(k4 + 1) * 132 + m] = a.y;
            As[(k4 + 2) * 132 + m] = a.z;
            As[(k4 + 3) * 132 + m] = a.w;
        }
        __syncthreads();

#pragma unroll
        for (int k = 0; k < 32; k++) {
            float4 xv = *(const float4*)&Xs[k * 68 + n0];
            float4 a0 = *(const float4*)&As[k * 132 + m0];
            float4 a1 = *(const float4*)&As[k * 132 + m0 + 4];
            float xr[4] = {xv.x, xv.y, xv.z, xv.w};
            float ar[8] = {a0.x, a0.y, a0.z, a0.w, a1.x, a1.y, a1.z, a1.w};
#pragma unroll
            for (int i = 0; i < 4; i++)
#pragma unroll
                for (int j = 0; j < 8; j++)
                    acc[i][j] = fmaf(xr[i], ar[j], acc[i][j]);
        }
        __syncthreads();
    }

    // stash S into smem [n][m] stride 132
    float* S = smem;
#pragma unroll
    for (int i = 0; i < 4; i++) {
        float4 s0 = make_float4(acc[i][0], acc[i][1], acc[i][2], acc[i][3]);
        float4 s1 = make_float4(acc[i][4], acc[i][5], acc[i][6], acc[i][7]);
        *(float4*)&S[(n0 + i) * 132 + m0]     = s0;
        *(float4*)&S[(n0 + i) * 132 + m0 + 4] = s1;
    }
    __syncthreads();

    // softmax over m (128) per row n; 8 warps x 8 rows each
    const int warp = tid >> 5;
    const int lane = tid & 31;
#pragma unroll
    for (int r = 0; r < 8; r++) {
        int n = warp * 8 + r;
        float v0 = S[n * 132 + lane];
        float v1 = S[n * 132 + lane + 32];
        float v2 = S[n * 132 + lane + 64];
        float v3 = S[n * 132 + lane + 96];
        float mx = fmaxf(fmaxf(v0, v1), fmaxf(v2, v3));
#pragma unroll
        for (int o = 16; o > 0; o >>= 1)
            mx = fmaxf(mx, __shfl_xor_sync(0xffffffffu, mx, o));
        float e0 = __expf(v0 - mx);
        float e1 = __expf(v1 - mx);
        float e2 = __expf(v2 - mx);
        float e3 = __expf(v3 - mx);
        float s = e0 + e1 + e2 + e3;
#pragma unroll
        for (int o = 16; o > 0; o >>= 1)
            s += __shfl_xor_sync(0xffffffffu, s, o);
        float inv = 1.0f / s;
        float* w = g_W + ((size_t)n * Cc + c) * Cc;
        w[lane]      = e0 * inv;
        w[lane + 32] = e1 * inv;
        w[lane + 64] = e2 * inv;
        w[lane + 96] = e3 * inv;
    }
}

// ---------------------------------------------------------------------------
// Kernel 2: out[n,c,f] = sum_m W[n,c,m] * X[n,m,f]
// Per block: fixed n, f-tile of 128; computes 128(c) x 128(f), K = m = 128.
// Grid: (16, 64), 256 threads, 8x8 micro-tile.
// ---------------------------------------------------------------------------
__global__ __launch_bounds__(256) void k_combine(const float* __restrict__ X,
                                                 float* __restrict__ out) {
    const int n    = blockIdx.y;
    const int fblk = blockIdx.x * 128;
    const int tid  = threadIdx.x;

    __shared__ float Ws[16 * 132];  // [k][c]
    __shared__ float Xs[16 * 132];  // [k][f]

    const int tf  = tid & 15;
    const int tc  = tid >> 4;
    const int c0  = tc * 8;
    const int f0l = tf * 8;

    float acc[8][8];
#pragma unroll
    for (int i = 0; i < 8; i++)
#pragma unroll
        for (int j = 0; j < 8; j++) acc[i][j] = 0.0f;

    const float* Wbase = g_W + (size_t)n * Cc * Cc;  // [c][m]
    const float* Xbase = X + (size_t)n * Cc * Ff;    // [m][f]

    for (int m0 = 0; m0 < Cc; m0 += 16) {
        // load W: 128(c) x 16(k) = 512 float4, 2 per thread; transpose into [k][c]
#pragma unroll
        for (int i = 0; i < 2; i++) {
            int v  = tid + i * 256;
            int cc = v >> 2;
            int k4 = (v & 3) * 4;
            float4 w = *(const float4*)&Wbase[(size_t)cc * Cc + m0 + k4];
            Ws[(k4 + 0) * 132 + cc] = w.x;
            Ws[(k4 + 1) * 132 + cc] = w.y;
            Ws[(k4 + 2) * 132 + cc] = w.z;
            Ws[(k4 + 3) * 132 + cc] = w.w;
        }
        // load X: 16(k) x 128(f) = 512 float4, 2 per thread; direct
#pragma unroll
        for (int i = 0; i < 2; i++) {
            int v  = tid + i * 256;
            int k  = v >> 5;
            int f4 = (v & 31) * 4;
            *(float4*)&Xs[k * 132 + f4] =
                *(const float4*)&Xbase[(size_t)(m0 + k) * Ff + fblk + f4];
        }
        __syncthreads();

#pragma unroll
        for (int k = 0; k < 16; k++) {
            float4 w0 = *(const float4*)&Ws[k * 132 + c0];
            float4 w1 = *(const float4*)&Ws[k * 132 + c0 + 4];
            float4 x0 = *(const float4*)&Xs[k * 132 + f0l];
            float4 x1 = *(const float4*)&Xs[k * 132 + f0l + 4];
            float wr[8] = {w0.x, w0.y, w0.z, w0.w, w1.x, w1.y, w1.z, w1.w};
            float xr[8] = {x0.x, x0.y, x0.z, x0.w, x1.x, x1.y, x1.z, x1.w};
#pragma unroll
            for (int i = 0; i < 8; i++)
#pragma unroll
                for (int j = 0; j < 8; j++)
                    acc[i][j] = fmaf(wr[i], xr[j], acc[i][j]);
        }
        __syncthreads();
    }

#pragma unroll
    for (int i = 0; i < 8; i++) {
        float* o = out + ((size_t)n * Cc + (c0 + i)) * Ff + fblk + f0l;
        float4 s0 = make_float4(acc[i][0], acc[i][1], acc[i][2], acc[i][3]);
        float4 s1 = make_float4(acc[i][4], acc[i][5], acc[i][6], acc[i][7]);
        *(float4*)&o[0] = s0;
        *(float4*)&o[4] = s1;
    }
}

extern "C" void kernel_launch(void* const* d_in, const int* in_sizes, int n_in,
                              void* d_out, int out_size) {
    const float* X = (const float*)d_in[0];
    const float* A = (const float*)d_in[1];
    float* out = (float*)d_out;
    (void)in_sizes; (void)n_in; (void)out_size;

    k_scores<<<128, 256>>>(X, A);
    k_combine<<<dim3(16, 64), 256>>>(X, out);
}

// round 4
// speedup vs baseline: 1.5686x; 1.5686x over previous
#include <cuda_runtime.h>
#include <cuda_bf16.h>
#include <cstdint>

#define Nn 64
#define Cc 128
#define Ff 2048

// Scratch: softmax weights W[n][c][m]  (4 MB)
__device__ float g_W[Nn * Cc * Cc];

// ---------------------------------------------------------------------------
// Portable tensor-core helpers (compile on compute_103; run as HMMA on sm_103a)
// ---------------------------------------------------------------------------
__device__ __forceinline__ uint32_t smem_u32(const void* p) {
    uint32_t a;
    asm("{ .reg .u64 t; cvta.to.shared.u64 t, %1; cvt.u32.u64 %0, t; }" : "=r"(a) : "l"(p));
    return a;
}

__device__ __forceinline__ void ldm4(uint32_t* r, uint32_t addr) {
    asm volatile("ldmatrix.sync.aligned.m8n8.x4.shared.b16 {%0,%1,%2,%3}, [%4];"
                 : "=r"(r[0]), "=r"(r[1]), "=r"(r[2]), "=r"(r[3]) : "r"(addr));
}

__device__ __forceinline__ void mma_bf16(float* d, const uint32_t* a, const uint32_t* b) {
    asm volatile(
        "mma.sync.aligned.m16n8k16.row.col.f32.bf16.bf16.f32 "
        "{%0,%1,%2,%3}, {%4,%5,%6,%7}, {%8,%9}, {%0,%1,%2,%3};"
        : "+f"(d[0]), "+f"(d[1]), "+f"(d[2]), "+f"(d[3])
        : "r"(a[0]), "r"(a[1]), "r"(a[2]), "r"(a[3]), "r"(b[0]), "r"(b[1]));
}

// fp32 -> bf16 (hi, lo) split; packs two adjacent K elements per u32
__device__ __forceinline__ void split2(float a, float b, uint32_t& hi, uint32_t& lo) {
    __nv_bfloat16 ha = __float2bfloat16(a), hb = __float2bfloat16(b);
    __nv_bfloat16 la = __float2bfloat16(a - __bfloat162float(ha));
    __nv_bfloat16 lb = __float2bfloat16(b - __bfloat162float(hb));
    __nv_bfloat162 H; H.x = ha; H.y = hb;
    __nv_bfloat162 L; L.x = la; L.y = lb;
    hi = *reinterpret_cast<uint32_t*>(&H);
    lo = *reinterpret_cast<uint32_t*>(&L);
}

// ---------------------------------------------------------------------------
// Kernel 1: per c (128 blocks, one wave): S[n=64][m=128] = sum_f X[n,c,f]*A[c,m,f]
// bf16-split HMMA, K=2048 in 32 double-buffered chunks of 64. Fused softmax -> g_W.
// smem bf16 tiles, row stride 72 elems (144B: conflict-free ldmatrix).
// ---------------------------------------------------------------------------
#define K1_SX 72
#define K1_XH 0
#define K1_XL 9216
#define K1_AH 18432
#define K1_AL 36864
#define K1_BUF 55296
#define K1_DYN (2 * K1_BUF)

__global__ __launch_bounds__(256) void k_scores(const float* __restrict__ X,
                                                const float* __restrict__ A) {
    extern __shared__ char sm[];
    const uint32_t sbase = smem_u32(sm);
    const int c = blockIdx.x, tid = threadIdx.x;
    const int wid = tid >> 5, lane = tid & 31;
    const int wn = wid & 1, wm = wid >> 1;  // warp tile: n 2x32, m 4x32

    float acc[2][4][4];
#pragma unroll
    for (int mb = 0; mb < 2; mb++)
#pragma unroll
        for (int nb = 0; nb < 4; nb++)
#pragma unroll
            for (int j = 0; j < 4; j++) acc[mb][nb][j] = 0.0f;

    const float* Ab = A + (size_t)c * Cc * Ff;  // [m][f]
    const float* Xb = X + (size_t)c * Ff;       // X[(n*Cc+c)*Ff]

    for (int i = 0; i < 33; i++) {
        if (i < 32) {
            const int f0 = i << 6;
            const int b = i & 1;
            __nv_bfloat16* Xh = (__nv_bfloat16*)(sm + b * K1_BUF + K1_XH);
            __nv_bfloat16* Xl = (__nv_bfloat16*)(sm + b * K1_BUF + K1_XL);
            __nv_bfloat16* Ah = (__nv_bfloat16*)(sm + b * K1_BUF + K1_AH);
            __nv_bfloat16* Al = (__nv_bfloat16*)(sm + b * K1_BUF + K1_AL);
#pragma unroll
            for (int it = 0; it < 4; it++) {
                int v = tid + it * 256, n = v >> 4, k4 = (v & 15) << 2;
                float4 x = *(const float4*)(Xb + (size_t)n * Cc * Ff + f0 + k4);
                uint32_t h01, l01, h23, l23;
                split2(x.x, x.y, h01, l01);
                split2(x.z, x.w, h23, l23);
                int e = n * K1_SX + k4;
                *(uint32_t*)(Xh + e) = h01; *(uint32_t*)(Xh + e + 2) = h23;
                *(uint32_t*)(Xl + e) = l01; *(uint32_t*)(Xl + e + 2) = l23;
            }
#pragma unroll
            for (int it = 0; it < 8; it++) {
                int v = tid + it * 256, m = v >> 4, k4 = (v & 15) << 2;
                float4 a = *(const float4*)(Ab + (size_t)m * Ff + f0 + k4);
                uint32_t h01, l01, h23, l23;
                split2(a.x, a.y, h01, l01);
                split2(a.z, a.w, h23, l23);
                int e = m * K1_SX + k4;
                *(uint32_t*)(Ah + e) = h01; *(uint32_t*)(Ah + e + 2) = h23;
                *(uint32_t*)(Al + e) = l01; *(uint32_t*)(Al + e + 2) = l23;
            }
        }
        if (i > 0) {
            const int b = (i - 1) & 1;
            const uint32_t xh = sbase + b * K1_BUF + K1_XH;
            const uint32_t xl = sbase + b * K1_BUF + K1_XL;
            const uint32_t ah = sbase + b * K1_BUF + K1_AH;
            const uint32_t al = sbase + b * K1_BUF + K1_AL;
#pragma unroll
            for (int ks = 0; ks < 4; ks++) {
                uint32_t xah[2][4], xal[2][4];
#pragma unroll
                for (int mb = 0; mb < 2; mb++) {
                    int row  = wn * 32 + mb * 16 + (lane & 15);
                    int koff = ks * 16 + ((lane >> 4) << 3);
                    uint32_t off = (uint32_t)(row * K1_SX + koff) * 2;
                    ldm4(xah[mb], xh + off);
                    ldm4(xal[mb], xl + off);
                }
                uint32_t bhf[2][4], blf[2][4];
#pragma unroll
                for (int g = 0; g < 2; g++) {
                    int row  = wm * 32 + g * 16 + ((lane >> 4) << 3) + (lane & 7);
                    int koff = ks * 16 + (((lane >> 3) & 1) << 3);
                    uint32_t off = (uint32_t)(row * K1_SX + koff) * 2;
                    ldm4(bhf[g], ah + off);
                    ldm4(blf[g], al + off);
                }
#pragma unroll
                for (int mb = 0; mb < 2; mb++)
#pragma unroll
                    for (int nb = 0; nb < 4; nb++) {
                        const uint32_t* Bh = &bhf[nb >> 1][(nb & 1) * 2];
                        const uint32_t* Bl = &blf[nb >> 1][(nb & 1) * 2];
                        mma_bf16(acc[mb][nb], xah[mb], Bh);
                        mma_bf16(acc[mb][nb], xah[mb], Bl);
                        mma_bf16(acc[mb][nb], xal[mb], Bh);
                    }
            }
        }
        __syncthreads();
    }

    // Epilogue: fragments -> smem S[n][m] (stride 132), then softmax over m.
    float* S = (float*)sm;
#pragma unroll
    for (int mb = 0; mb < 2; mb++)
#pragma unroll
        for (int nb = 0; nb < 4; nb++) {
            int n = wn * 32 + mb * 16 + (lane >> 2);
            int m = wm * 32 + nb * 8 + (lane & 3) * 2;
            S[n * 132 + m]           = acc[mb][nb][0];
            S[n * 132 + m + 1]       = acc[mb][nb][1];
            S[(n + 8) * 132 + m]     = acc[mb][nb][2];
            S[(n + 8) * 132 + m + 1] = acc[mb][nb][3];
        }
    __syncthreads();

#pragma unroll
    for (int r = 0; r < 8; r++) {
        int n = wid * 8 + r;
        float v0 = S[n * 132 + lane];
        float v1 = S[n * 132 + lane + 32];
        float v2 = S[n * 132 + lane + 64];
        float v3 = S[n * 132 + lane + 96];
        float mx = fmaxf(fmaxf(v0, v1), fmaxf(v2, v3));
#pragma unroll
        for (int o = 16; o > 0; o >>= 1)
            mx = fmaxf(mx, __shfl_xor_sync(0xffffffffu, mx, o));
        float e0 = __expf(v0 - mx);
        float e1 = __expf(v1 - mx);
        float e2 = __expf(v2 - mx);
        float e3 = __expf(v3 - mx);
        float s = e0 + e1 + e2 + e3;
#pragma unroll
        for (int o = 16; o > 0; o >>= 1)
            s += __shfl_xor_sync(0xffffffffu, s, o);
        float inv = 1.0f / s;
        float* w = g_W + ((size_t)n * Cc + c) * Cc;
        w[lane]      = e0 * inv;
        w[lane + 32] = e1 * inv;
        w[lane + 64] = e2 * inv;
        w[lane + 96] = e3 * inv;
    }
}

// ---------------------------------------------------------------------------
// Kernel 2: per (n, f-tile 128): out[c=128][f=128] = sum_m W[n,c,m]*X[n,m,f]
// K = m = 128 fully resident. X transposed to [f][m] during the load.
// smem row stride 136 elems (272B: conflict-free ldmatrix, 4-way store max).
// ---------------------------------------------------------------------------
#define K2_S 136
#define K2_WH 0
#define K2_WL 34816
#define K2_TH 69632
#define K2_TL 104448
#define K2_DYN 139264

__global__ __launch_bounds__(256) void k_combine(const float* __restrict__ X,
                                                 float* __restrict__ out) {
    extern __shared__ char sm[];
    const uint32_t sbase = smem_u32(sm);
    const int n = blockIdx.y, fblk = blockIdx.x * 128;
    const int tid = threadIdx.x;
    const int wid = tid >> 5, lane = tid & 31;
    const int wm = wid >> 1, wf = wid & 1;  // warp tile: c 4x32, f 2x64

    __nv_bfloat16* Wh = (__nv_bfloat16*)(sm + K2_WH);
    __nv_bfloat16* Wl = (__nv_bfloat16*)(sm + K2_WL);
    __nv_bfloat16* Th = (__nv_bfloat16*)(sm + K2_TH);
    __nv_bfloat16* Tl = (__nv_bfloat16*)(sm + K2_TL);

    // W[n]: [c][m] fp32, coalesced, split -> Wh/Wl [c][m]
    const float* Wb = g_W + (size_t)n * Cc * Cc;
#pragma unroll
    for (int it = 0; it < 16; it++) {
        int v = tid + it * 256, row = v >> 5, k4 = (v & 31) << 2;
        float4 w = *(const float4*)(Wb + (size_t)row * Cc + k4);
        uint32_t h01, l01, h23, l23;
        split2(w.x, w.y, h01, l01);
        split2(w.z, w.w, h23, l23);
        int e = row * K2_S + k4;
        *(uint32_t*)(Wh + e) = h01; *(uint32_t*)(Wh + e + 2) = h23;
        *(uint32_t*)(Wl + e) = l01; *(uint32_t*)(Wl + e + 2) = l23;
    }
    // X[n]: [m][f] fp32; coalesced along f (4 m-rows per item), transpose-store
    // 4 bf16 contiguous in [f][m] layout per tile.
    const float* Xb = X + (size_t)n * Cc * Ff + fblk;
#pragma unroll
    for (int it = 0; it < 16; it++) {
        int v = tid + it * 256;
        int f = v & 127, m4 = (v >> 7) << 2;
        float x0 = Xb[(size_t)(m4 + 0) * Ff + f];
        float x1 = Xb[(size_t)(m4 + 1) * Ff + f];
        float x2 = Xb[(size_t)(m4 + 2) * Ff + f];
        float x3 = Xb[(size_t)(m4 + 3) * Ff + f];
        uint32_t h01, l01, h23, l23;
        split2(x0, x1, h01, l01);
        split2(x2, x3, h23, l23);
        int e = f * K2_S + m4;
        *(uint32_t*)(Th + e) = h01; *(uint32_t*)(Th + e + 2) = h23;
        *(uint32_t*)(Tl + e) = l01; *(uint32_t*)(Tl + e + 2) = l23;
    }
    __syncthreads();

    float acc[2][8][4];
#pragma unroll
    for (int mb = 0; mb < 2; mb++)
#pragma unroll
        for (int nb = 0; nb < 8; nb++)
#pragma unroll
            for (int j = 0; j < 4; j++) acc[mb][nb][j] = 0.0f;

    const uint32_t wh = sbase + K2_WH, wl = sbase + K2_WL;
    const uint32_t th = sbase + K2_TH, tl = sbase + K2_TL;

#pragma unroll
    for (int ks = 0; ks < 8; ks++) {
        uint32_t wah[2][4], wal[2][4];
#pragma unroll
        for (int mb = 0; mb < 2; mb++) {
            int row  = wm * 32 + mb * 16 + (lane & 15);
            int koff = ks * 16 + ((lane >> 4) << 3);
            uint32_t off = (uint32_t)(row * K2_S + koff) * 2;
            ldm4(wah[mb], wh + off);
            ldm4(wal[mb], wl + off);
        }
#pragma unroll
        for (int g = 0; g < 4; g++) {
            uint32_t bhf[4], blf[4];
            int row  = wf * 64 + g * 16 + ((lane >> 4) << 3) + (lane & 7);
            int koff = ks * 16 + (((lane >> 3) & 1) << 3);
            uint32_t off = (uint32_t)(row * K2_S + koff) * 2;
            ldm4(bhf, th + off);
            ldm4(blf, tl + off);
#pragma unroll
            for (int mb = 0; mb < 2; mb++)
#pragma unroll
                for (int h = 0; h < 2; h++) {
                    int nb = g * 2 + h;
                    mma_bf16(acc[mb][nb], wah[mb], &bhf[h * 2]);
                    mma_bf16(acc[mb][nb], wah[mb], &blf[h * 2]);
                    mma_bf16(acc[mb][nb], wal[mb], &bhf[h * 2]);
                }
        }
    }
    __syncthreads();  // tiles done being read; reuse smem for S

    // fragments -> smem S[c][f] (stride 132) -> coalesced float4 stores
    float* S = (float*)sm;
#pragma unroll
    for (int mb = 0; mb < 2; mb++)
#pragma unroll
        for (int nb = 0; nb < 8; nb++) {
            int cc = wm * 32 + mb * 16 + (lane >> 2);
            int f  = wf * 64 + nb * 8 + (lane & 3) * 2;
            *(float2*)&S[cc * 132 + f]       = make_float2(acc[mb][nb][0], acc[mb][nb][1]);
            *(float2*)&S[(cc + 8) * 132 + f] = make_float2(acc[mb][nb][2], acc[mb][nb][3]);
        }
    __syncthreads();

#pragma unroll
    for (int it = 0; it < 16; it++) {
        int v = tid + it * 256, row = v >> 5, f4 = (v & 31) << 2;
        float4 val = *(const float4*)&S[row * 132 + f4];
        *(float4*)(out + ((size_t)n * Cc + row) * Ff + fblk + f4) = val;
    }
}

extern "C" void kernel_launch(void* const* d_in, const int* in_sizes, int n_in,
                              void* d_out, int out_size) {
    const float* X = (const float*)d_in[0];
    const float* A = (const float*)d_in[1];
    float* out = (float*)d_out;
    (void)in_sizes; (void)n_in; (void)out_size;

    cudaFuncSetAttribute(k_scores, cudaFuncAttributeMaxDynamicSharedMemorySize, K1_DYN);
    cudaFuncSetAttribute(k_combine, cudaFuncAttributeMaxDynamicSharedMemorySize, K2_DYN);

    k_scores<<<128, 256, K1_DYN>>>(X, A);
    k_combine<<<dim3(16, 64), 256, K2_DYN>>>(X, out);
}

// round 5
// speedup vs baseline: 2.5774x; 1.6432x over previous
#include <cuda_runtime.h>
#include <cuda_bf16.h>
#include <cstdint>

#define Nn 64
#define Cc 128
#define Ff 2048

// Scratch: partial scores (2 K-slabs, fp32) + softmax weights
__device__ float g_S[2 * Nn * Cc * Cc];  // 8 MB
__device__ float g_W[Nn * Cc * Cc];      // 4 MB
#define SLAB ((size_t)Nn * Cc * Cc)

// ---------------------------------------------------------------------------
// Portable tensor-core helpers (compile on compute_103; run on sm_103a)
// ---------------------------------------------------------------------------
__device__ __forceinline__ uint32_t smem_u32(const void* p) {
    uint32_t a;
    asm("{ .reg .u64 t; cvta.to.shared.u64 t, %1; cvt.u32.u64 %0, t; }" : "=r"(a) : "l"(p));
    return a;
}

__device__ __forceinline__ void ldm4(uint32_t* r, uint32_t addr) {
    asm volatile("ldmatrix.sync.aligned.m8n8.x4.shared.b16 {%0,%1,%2,%3}, [%4];"
                 : "=r"(r[0]), "=r"(r[1]), "=r"(r[2]), "=r"(r[3]) : "r"(addr));
}

__device__ __forceinline__ void mma_bf16(float* d, const uint32_t* a, const uint32_t* b) {
    asm volatile(
        "mma.sync.aligned.m16n8k16.row.col.f32.bf16.bf16.f32 "
        "{%0,%1,%2,%3}, {%4,%5,%6,%7}, {%8,%9}, {%0,%1,%2,%3};"
        : "+f"(d[0]), "+f"(d[1]), "+f"(d[2]), "+f"(d[3])
        : "r"(a[0]), "r"(a[1]), "r"(a[2]), "r"(a[3]), "r"(b[0]), "r"(b[1]));
}

// fp32 -> bf16 (hi, lo) split; packs two adjacent K elements per u32
__device__ __forceinline__ void split2(float a, float b, uint32_t& hi, uint32_t& lo) {
    __nv_bfloat16 ha = __float2bfloat16(a), hb = __float2bfloat16(b);
    __nv_bfloat16 la = __float2bfloat16(a - __bfloat162float(ha));
    __nv_bfloat16 lb = __float2bfloat16(b - __bfloat162float(hb));
    __nv_bfloat162 H; H.x = ha; H.y = hb;
    __nv_bfloat162 L; L.x = la; L.y = lb;
    hi = *reinterpret_cast<uint32_t*>(&H);
    lo = *reinterpret_cast<uint32_t*>(&L);
}

// ---------------------------------------------------------------------------
// Kernel 1: grid (c=128, kh=2), 512 threads. Each block:
// S_part[n=64][m=128] = sum_{f in kh-half} X[n,c,f]*A[c,m,f], K=1024 in 16
// double-buffered chunks of 64. Result -> g_S slab (fp32). Softmax deferred.
// Warp tile: n 2x32, m 8x16.
// ---------------------------------------------------------------------------
#define K1_SX 72
#define K1_XH 0
#define K1_XL 9216
#define K1_AH 18432
#define K1_AL 36864
#define K1_BUF 55296
#define K1_DYN (2 * K1_BUF)

__global__ __launch_bounds__(512) void k_scores(const float* __restrict__ X,
                                                const float* __restrict__ A) {
    extern __shared__ char sm[];
    const uint32_t sbase = smem_u32(sm);
    const int c = blockIdx.x, kh = blockIdx.y;
    const int tid = threadIdx.x;
    const int wid = tid >> 5, lane = tid & 31;
    const int wn = wid & 1, wm = wid >> 1;  // n0 = wn*32, m0 = wm*16

    float acc[2][2][4];
#pragma unroll
    for (int nb = 0; nb < 2; nb++)
#pragma unroll
        for (int mb = 0; mb < 2; mb++)
#pragma unroll
            for (int j = 0; j < 4; j++) acc[nb][mb][j] = 0.0f;

    const float* Ab = A + (size_t)c * Cc * Ff + kh * 1024;  // [m][f]
    const float* Xb = X + (size_t)c * Ff + kh * 1024;       // X[(n*Cc+c)*Ff]

    for (int i = 0; i < 17; i++) {
        if (i < 16) {
            const int f0 = i << 6;
            const int b = i & 1;
            __nv_bfloat16* Xh = (__nv_bfloat16*)(sm + b * K1_BUF + K1_XH);
            __nv_bfloat16* Xl = (__nv_bfloat16*)(sm + b * K1_BUF + K1_XL);
            __nv_bfloat16* Ah = (__nv_bfloat16*)(sm + b * K1_BUF + K1_AH);
            __nv_bfloat16* Al = (__nv_bfloat16*)(sm + b * K1_BUF + K1_AL);
#pragma unroll
            for (int it = 0; it < 2; it++) {
                int v = tid + it * 512, n = v >> 4, k4 = (v & 15) << 2;
                float4 x = *(const float4*)(Xb + (size_t)n * Cc * Ff + f0 + k4);
                uint32_t h01, l01, h23, l23;
                split2(x.x, x.y, h01, l01);
                split2(x.z, x.w, h23, l23);
                int e = n * K1_SX + k4;
                *(uint32_t*)(Xh + e) = h01; *(uint32_t*)(Xh + e + 2) = h23;
                *(uint32_t*)(Xl + e) = l01; *(uint32_t*)(Xl + e + 2) = l23;
            }
#pragma unroll
            for (int it = 0; it < 4; it++) {
                int v = tid + it * 512, m = v >> 4, k4 = (v & 15) << 2;
                float4 a = *(const float4*)(Ab + (size_t)m * Ff + f0 + k4);
                uint32_t h01, l01, h23, l23;
                split2(a.x, a.y, h01, l01);
                split2(a.z, a.w, h23, l23);
                int e = m * K1_SX + k4;
                *(uint32_t*)(Ah + e) = h01; *(uint32_t*)(Ah + e + 2) = h23;
                *(uint32_t*)(Al + e) = l01; *(uint32_t*)(Al + e + 2) = l23;
            }
        }
        if (i > 0) {
            const int b = (i - 1) & 1;
            const uint32_t xh = sbase + b * K1_BUF + K1_XH;
            const uint32_t xl = sbase + b * K1_BUF + K1_XL;
            const uint32_t ah = sbase + b * K1_BUF + K1_AH;
            const uint32_t al = sbase + b * K1_BUF + K1_AL;
#pragma unroll
            for (int ks = 0; ks < 4; ks++) {
                uint32_t xah[2][4], xal[2][4];
#pragma unroll
                for (int nb = 0; nb < 2; nb++) {
                    int row  = wn * 32 + nb * 16 + (lane & 15);
                    int koff = ks * 16 + ((lane >> 4) << 3);
                    uint32_t off = (uint32_t)(row * K1_SX + koff) * 2;
                    ldm4(xah[nb], xh + off);
                    ldm4(xal[nb], xl + off);
                }
                uint32_t bhf[4], blf[4];
                {
                    int row  = wm * 16 + ((lane >> 4) << 3) + (lane & 7);
                    int koff = ks * 16 + (((lane >> 3) & 1) << 3);
                    uint32_t off = (uint32_t)(row * K1_SX + koff) * 2;
                    ldm4(bhf, ah + off);
                    ldm4(blf, al + off);
                }
#pragma unroll
                for (int nb = 0; nb < 2; nb++)
#pragma unroll
                    for (int mb = 0; mb < 2; mb++) {
                        mma_bf16(acc[nb][mb], xah[nb], &bhf[mb * 2]);
                        mma_bf16(acc[nb][mb], xah[nb], &blf[mb * 2]);
                        mma_bf16(acc[nb][mb], xal[nb], &bhf[mb * 2]);
                    }
            }
        }
        __syncthreads();
    }

    // fragments -> smem S[n][m] (stride 132) -> coalesced fp32 stores to slab
    float* S = (float*)sm;
#pragma unroll
    for (int nb = 0; nb < 2; nb++)
#pragma unroll
        for (int mb = 0; mb < 2; mb++) {
            int n = wn * 32 + nb * 16 + (lane >> 2);
            int m = wm * 16 + mb * 8 + (lane & 3) * 2;
            S[n * 132 + m]           = acc[nb][mb][0];
            S[n * 132 + m + 1]       = acc[nb][mb][1];
            S[(n + 8) * 132 + m]     = acc[nb][mb][2];
            S[(n + 8) * 132 + m + 1] = acc[nb][mb][3];
        }
    __syncthreads();

    float* slab = g_S + (size_t)kh * SLAB;
#pragma unroll
    for (int it = 0; it < 4; it++) {
        int v = tid + it * 512, n = v >> 5, m4 = (v & 31) << 2;
        float4 val = *(const float4*)&S[n * 132 + m4];
        *(float4*)(slab + ((size_t)n * Cc + c) * Cc + m4) = val;
    }
}

// ---------------------------------------------------------------------------
// Softmax: combine the two K-slabs, softmax over m (128), write g_W.
// grid 256 x 256 threads; 32 rows per block, one row per warp x 4.
// ---------------------------------------------------------------------------
__global__ __launch_bounds__(256) void k_softmax() {
    const int tid = threadIdx.x, wid = tid >> 5, lane = tid & 31;
    const int r0 = blockIdx.x * 32 + wid * 4;
#pragma unroll
    for (int j = 0; j < 4; j++) {
        int r = r0 + j;
        size_t base = (size_t)r * Cc;  // r = n*Cc + c
        float v0 = g_S[base + lane]      + g_S[SLAB + base + lane];
        float v1 = g_S[base + lane + 32] + g_S[SLAB + base + lane + 32];
        float v2 = g_S[base + lane + 64] + g_S[SLAB + base + lane + 64];
        float v3 = g_S[base + lane + 96] + g_S[SLAB + base + lane + 96];
        float mx = fmaxf(fmaxf(v0, v1), fmaxf(v2, v3));
#pragma unroll
        for (int o = 16; o > 0; o >>= 1)
            mx = fmaxf(mx, __shfl_xor_sync(0xffffffffu, mx, o));
        float e0 = __expf(v0 - mx);
        float e1 = __expf(v1 - mx);
        float e2 = __expf(v2 - mx);
        float e3 = __expf(v3 - mx);
        float s = e0 + e1 + e2 + e3;
#pragma unroll
        for (int o = 16; o > 0; o >>= 1)
            s += __shfl_xor_sync(0xffffffffu, s, o);
        float inv = 1.0f / s;
        g_W[base + lane]      = e0 * inv;
        g_W[base + lane + 32] = e1 * inv;
        g_W[base + lane + 64] = e2 * inv;
        g_W[base + lane + 96] = e3 * inv;
    }
}

// ---------------------------------------------------------------------------
// Kernel 2: per (n, f-tile 128), 512 threads: out[c=128][f=128] = sum_m W*X.
// K = m = 128 resident. Warp tile: c 4x32, f 4x32.
// ---------------------------------------------------------------------------
#define K2_S 136
#define K2_WH 0
#define K2_WL 34816
#define K2_TH 69632
#define K2_TL 104448
#define K2_DYN 139264

__global__ __launch_bounds__(512) void k_combine(const float* __restrict__ X,
                                                 float* __restrict__ out) {
    extern __shared__ char sm[];
    const uint32_t sbase = smem_u32(sm);
    const int n = blockIdx.y, fblk = blockIdx.x * 128;
    const int tid = threadIdx.x;
    const int wid = tid >> 5, lane = tid & 31;
    const int wm = wid >> 2, wf = wid & 3;  // c0 = wm*32, f0 = wf*32

    __nv_bfloat16* Wh = (__nv_bfloat16*)(sm + K2_WH);
    __nv_bfloat16* Wl = (__nv_bfloat16*)(sm + K2_WL);
    __nv_bfloat16* Th = (__nv_bfloat16*)(sm + K2_TH);
    __nv_bfloat16* Tl = (__nv_bfloat16*)(sm + K2_TL);

    const float* Wb = g_W + (size_t)n * Cc * Cc;
#pragma unroll
    for (int it = 0; it < 8; it++) {
        int v = tid + it * 512, row = v >> 5, k4 = (v & 31) << 2;
        float4 w = *(const float4*)(Wb + (size_t)row * Cc + k4);
        uint32_t h01, l01, h23, l23;
        split2(w.x, w.y, h01, l01);
        split2(w.z, w.w, h23, l23);
        int e = row * K2_S + k4;
        *(uint32_t*)(Wh + e) = h01; *(uint32_t*)(Wh + e + 2) = h23;
        *(uint32_t*)(Wl + e) = l01; *(uint32_t*)(Wl + e + 2) = l23;
    }
    const float* Xb = X + (size_t)n * Cc * Ff + fblk;
#pragma unroll
    for (int it = 0; it < 8; it++) {
        int v = tid + it * 512;
        int f = v & 127, m4 = (v >> 7) << 2;
        float x0 = Xb[(size_t)(m4 + 0) * Ff + f];
        float x1 = Xb[(size_t)(m4 + 1) * Ff + f];
        float x2 = Xb[(size_t)(m4 + 2) * Ff + f];
        float x3 = Xb[(size_t)(m4 + 3) * Ff + f];
        uint32_t h01, l01, h23, l23;
        split2(x0, x1, h01, l01);
        split2(x2, x3, h23, l23);
        int e = f * K2_S + m4;
        *(uint32_t*)(Th + e) = h01; *(uint32_t*)(Th + e + 2) = h23;
        *(uint32_t*)(Tl + e) = l01; *(uint32_t*)(Tl + e + 2) = l23;
    }
    __syncthreads();

    float acc[2][4][4];
#pragma unroll
    for (int nb = 0; nb < 2; nb++)
#pragma unroll
        for (int fb = 0; fb < 4; fb++)
#pragma unroll
            for (int j = 0; j < 4; j++) acc[nb][fb][j] = 0.0f;

    const uint32_t wh = sbase + K2_WH, wl = sbase + K2_WL;
    const uint32_t th = sbase + K2_TH, tl = sbase + K2_TL;

#pragma unroll
    for (int ks = 0; ks < 8; ks++) {
        uint32_t wah[2][4], wal[2][4];
#pragma unroll
        for (int nb = 0; nb < 2; nb++) {
            int row  = wm * 32 + nb * 16 + (lane & 15);
            int koff = ks * 16 + ((lane >> 4) << 3);
            uint32_t off = (uint32_t)(row * K2_S + koff) * 2;
            ldm4(wah[nb], wh + off);
            ldm4(wal[nb], wl + off);
        }
        uint32_t bhf[2][4], blf[2][4];
#pragma unroll
        for (int g = 0; g < 2; g++) {
            int row  = wf * 32 + g * 16 + ((lane >> 4) << 3) + (lane & 7);
            int koff = ks * 16 + (((lane >> 3) & 1) << 3);
            uint32_t off = (uint32_t)(row * K2_S + koff) * 2;
            ldm4(bhf[g], th + off);
            ldm4(blf[g], tl + off);
        }
#pragma unroll
        for (int nb = 0; nb < 2; nb++)
#pragma unroll
            for (int g = 0; g < 2; g++)
#pragma unroll
                for (int h = 0; h < 2; h++) {
                    int fb = g * 2 + h;
                    mma_bf16(acc[nb][fb], wah[nb], &bhf[g][h * 2]);
                    mma_bf16(acc[nb][fb], wah[nb], &blf[g][h * 2]);
                    mma_bf16(acc[nb][fb], wal[nb], &bhf[g][h * 2]);
                }
    }
    __syncthreads();  // tiles done; reuse smem

    float* S = (float*)sm;
#pragma unroll
    for (int nb = 0; nb < 2; nb++)
#pragma unroll
        for (int fb = 0; fb < 4; fb++) {
            int cc = wm * 32 + nb * 16 + (lane >> 2);
            int f  = wf * 32 + fb * 8 + (lane & 3) * 2;
            *(float2*)&S[cc * 132 + f]       = make_float2(acc[nb][fb][0], acc[nb][fb][1]);
            *(float2*)&S[(cc + 8) * 132 + f] = make_float2(acc[nb][fb][2], acc[nb][fb][3]);
        }
    __syncthreads();

#pragma unroll
    for (int it = 0; it < 8; it++) {
        int v = tid + it * 512, row = v >> 5, f4 = (v & 31) << 2;
        float4 val = *(const float4*)&S[row * 132 + f4];
        *(float4*)(out + ((size_t)n * Cc + row) * Ff + fblk + f4) = val;
    }
}

extern "C" void kernel_launch(void* const* d_in, const int* in_sizes, int n_in,
                              void* d_out, int out_size) {
    const float* X = (const float*)d_in[0];
    const float* A = (const float*)d_in[1];
    float* out = (float*)d_out;
    (void)in_sizes; (void)n_in; (void)out_size;

    cudaFuncSetAttribute(k_scores, cudaFuncAttributeMaxDynamicSharedMemorySize, K1_DYN);
    cudaFuncSetAttribute(k_combine, cudaFuncAttributeMaxDynamicSharedMemorySize, K2_DYN);

    k_scores<<<dim3(128, 2), 512, K1_DYN>>>(X, A);
    k_softmax<<<256, 256>>>();
    k_combine<<<dim3(16, 64), 512, K2_DYN>>>(X, out);
}

// round 6
// speedup vs baseline: 2.8707x; 1.1138x over previous
#include <cuda_runtime.h>
#include <cuda_bf16.h>
#include <cstdint>

#define Nn 64
#define Cc 128
#define Ff 2048

// Scratch: partial scores (2 K-slabs, fp32) + softmax weights
__device__ float g_S[2 * Nn * Cc * Cc];  // 8 MB
__device__ float g_W[Nn * Cc * Cc];      // 4 MB
#define SLAB ((size_t)Nn * Cc * Cc)

// ---------------------------------------------------------------------------
// Portable tensor-core helpers
// ---------------------------------------------------------------------------
__device__ __forceinline__ uint32_t smem_u32(const void* p) {
    uint32_t a;
    asm("{ .reg .u64 t; cvta.to.shared.u64 t, %1; cvt.u32.u64 %0, t; }" : "=r"(a) : "l"(p));
    return a;
}

__device__ __forceinline__ void ldm4(uint32_t* r, uint32_t addr) {
    asm volatile("ldmatrix.sync.aligned.m8n8.x4.shared.b16 {%0,%1,%2,%3}, [%4];"
                 : "=r"(r[0]), "=r"(r[1]), "=r"(r[2]), "=r"(r[3]) : "r"(addr));
}
__device__ __forceinline__ void ldm4t(uint32_t* r, uint32_t addr) {
    asm volatile("ldmatrix.sync.aligned.m8n8.x4.trans.shared.b16 {%0,%1,%2,%3}, [%4];"
                 : "=r"(r[0]), "=r"(r[1]), "=r"(r[2]), "=r"(r[3]) : "r"(addr));
}

__device__ __forceinline__ void mma_bf16(float* d, const uint32_t* a, const uint32_t* b) {
    asm volatile(
        "mma.sync.aligned.m16n8k16.row.col.f32.bf16.bf16.f32 "
        "{%0,%1,%2,%3}, {%4,%5,%6,%7}, {%8,%9}, {%0,%1,%2,%3};"
        : "+f"(d[0]), "+f"(d[1]), "+f"(d[2]), "+f"(d[3])
        : "r"(a[0]), "r"(a[1]), "r"(a[2]), "r"(a[3]), "r"(b[0]), "r"(b[1]));
}

// fp32 -> bf16 (hi, lo) split via packed cvt; low bf16 = first element
__device__ __forceinline__ void split2(float a, float b, uint32_t& hi, uint32_t& lo) {
    asm("cvt.rn.bf16x2.f32 %0, %1, %2;" : "=r"(hi) : "f"(b), "f"(a));
    float ha = __uint_as_float(hi << 16);
    float hb = __uint_as_float(hi & 0xffff0000u);
    float ra = a - ha;
    float rb = b - hb;
    asm("cvt.rn.bf16x2.f32 %0, %1, %2;" : "=r"(lo) : "f"(rb), "f"(ra));
}

// ---------------------------------------------------------------------------
// Kernel 1: grid (c=128, kh=2), 512 threads, 2 CTAs/SM (entire grid resident).
// S_part[n=64][m=128] = sum_{f in kh-half} X*A, K=1024 in 32 double-buffered
// chunks of 32. Row stride 40 elems (80B: conflict-free ldmatrix).
// Warp tile: n 2x32, m 8x16.
// ---------------------------------------------------------------------------
#define K1_SX 40
#define K1_XH 0
#define K1_XL 5120
#define K1_AH 10240
#define K1_AL 20480
#define K1_BUF 30720
#define K1_DYN (2 * K1_BUF)

__global__ __launch_bounds__(512, 2) void k_scores(const float* __restrict__ X,
                                                   const float* __restrict__ A) {
    extern __shared__ char sm[];
    const uint32_t sbase = smem_u32(sm);
    const int c = blockIdx.x, kh = blockIdx.y;
    const int tid = threadIdx.x;
    const int wid = tid >> 5, lane = tid & 31;
    const int wn = wid & 1, wm = wid >> 1;  // n0 = wn*32, m0 = wm*16

    float acc[2][2][4];
#pragma unroll
    for (int nb = 0; nb < 2; nb++)
#pragma unroll
        for (int mb = 0; mb < 2; mb++)
#pragma unroll
            for (int j = 0; j < 4; j++) acc[nb][mb][j] = 0.0f;

    const float* Ab = A + (size_t)c * Cc * Ff + kh * 1024;  // [m][f]
    const float* Xb = X + (size_t)c * Ff + kh * 1024;       // X[(n*Cc+c)*Ff]

    // per-thread load coords
    const int xr = tid >> 3, xk = (tid & 7) << 2;  // X: 64 rows x 8 thr

    for (int i = 0; i < 33; i++) {
        if (i < 32) {
            const int f0 = i << 5;
            const int b = i & 1;
            __nv_bfloat16* Xh = (__nv_bfloat16*)(sm + b * K1_BUF + K1_XH);
            __nv_bfloat16* Xl = (__nv_bfloat16*)(sm + b * K1_BUF + K1_XL);
            __nv_bfloat16* Ah = (__nv_bfloat16*)(sm + b * K1_BUF + K1_AH);
            __nv_bfloat16* Al = (__nv_bfloat16*)(sm + b * K1_BUF + K1_AL);
            {
                float4 x = *(const float4*)(Xb + (size_t)xr * Cc * Ff + f0 + xk);
                uint32_t h01, l01, h23, l23;
                split2(x.x, x.y, h01, l01);
                split2(x.z, x.w, h23, l23);
                int e = xr * K1_SX + xk;
                *(uint2*)(Xh + e) = make_uint2(h01, h23);
                *(uint2*)(Xl + e) = make_uint2(l01, l23);
            }
#pragma unroll
            for (int it = 0; it < 2; it++) {
                int v = tid + it * 512, m = v >> 3, k4 = (v & 7) << 2;
                float4 a = *(const float4*)(Ab + (size_t)m * Ff + f0 + k4);
                uint32_t h01, l01, h23, l23;
                split2(a.x, a.y, h01, l01);
                split2(a.z, a.w, h23, l23);
                int e = m * K1_SX + k4;
                *(uint2*)(Ah + e) = make_uint2(h01, h23);
                *(uint2*)(Al + e) = make_uint2(l01, l23);
            }
        }
        if (i > 0) {
            const int b = (i - 1) & 1;
            const uint32_t xh = sbase + b * K1_BUF + K1_XH;
            const uint32_t xl = sbase + b * K1_BUF + K1_XL;
            const uint32_t ah = sbase + b * K1_BUF + K1_AH;
            const uint32_t al = sbase + b * K1_BUF + K1_AL;
#pragma unroll
            for (int ks = 0; ks < 2; ks++) {
                uint32_t xah[2][4], xal[2][4];
#pragma unroll
                for (int nb = 0; nb < 2; nb++) {
                    int row  = wn * 32 + nb * 16 + (lane & 15);
                    int koff = ks * 16 + ((lane >> 4) << 3);
                    uint32_t off = (uint32_t)(row * K1_SX + koff) * 2;
                    ldm4(xah[nb], xh + off);
                    ldm4(xal[nb], xl + off);
                }
                uint32_t bhf[4], blf[4];
                {
                    int row  = wm * 16 + ((lane >> 4) << 3) + (lane & 7);
                    int koff = ks * 16 + (((lane >> 3) & 1) << 3);
                    uint32_t off = (uint32_t)(row * K1_SX + koff) * 2;
                    ldm4(bhf, ah + off);
                    ldm4(blf, al + off);
                }
#pragma unroll
                for (int nb = 0; nb < 2; nb++)
#pragma unroll
                    for (int mb = 0; mb < 2; mb++) {
                        mma_bf16(acc[nb][mb], xah[nb], &bhf[mb * 2]);
                        mma_bf16(acc[nb][mb], xah[nb], &blf[mb * 2]);
                        mma_bf16(acc[nb][mb], xal[nb], &bhf[mb * 2]);
                    }
            }
        }
        __syncthreads();
    }

    // fragments -> smem S[n][m] (stride 132) -> coalesced fp32 stores to slab
    float* S = (float*)sm;
#pragma unroll
    for (int nb = 0; nb < 2; nb++)
#pragma unroll
        for (int mb = 0; mb < 2; mb++) {
            int n = wn * 32 + nb * 16 + (lane >> 2);
            int m = wm * 16 + mb * 8 + (lane & 3) * 2;
            S[n * 132 + m]           = acc[nb][mb][0];
            S[n * 132 + m + 1]       = acc[nb][mb][1];
            S[(n + 8) * 132 + m]     = acc[nb][mb][2];
            S[(n + 8) * 132 + m + 1] = acc[nb][mb][3];
        }
    __syncthreads();

    float* slab = g_S + (size_t)kh * SLAB;
#pragma unroll
    for (int it = 0; it < 4; it++) {
        int v = tid + it * 512, n = v >> 5, m4 = (v & 31) << 2;
        float4 val = *(const float4*)&S[n * 132 + m4];
        *(float4*)(slab + ((size_t)n * Cc + c) * Cc + m4) = val;
    }
}

// ---------------------------------------------------------------------------
// Softmax: combine the two K-slabs, softmax over m (128), write g_W.
// ---------------------------------------------------------------------------
__global__ __launch_bounds__(256) void k_softmax() {
    const int tid = threadIdx.x, wid = tid >> 5, lane = tid & 31;
    const int r0 = blockIdx.x * 32 + wid * 4;
#pragma unroll
    for (int j = 0; j < 4; j++) {
        int r = r0 + j;
        size_t base = (size_t)r * Cc;
        float v0 = g_S[base + lane]      + g_S[SLAB + base + lane];
        float v1 = g_S[base + lane + 32] + g_S[SLAB + base + lane + 32];
        float v2 = g_S[base + lane + 64] + g_S[SLAB + base + lane + 64];
        float v3 = g_S[base + lane + 96] + g_S[SLAB + base + lane + 96];
        float mx = fmaxf(fmaxf(v0, v1), fmaxf(v2, v3));
#pragma unroll
        for (int o = 16; o > 0; o >>= 1)
            mx = fmaxf(mx, __shfl_xor_sync(0xffffffffu, mx, o));
        float e0 = __expf(v0 - mx);
        float e1 = __expf(v1 - mx);
        float e2 = __expf(v2 - mx);
        float e3 = __expf(v3 - mx);
        float s = e0 + e1 + e2 + e3;
#pragma unroll
        for (int o = 16; o > 0; o >>= 1)
            s += __shfl_xor_sync(0xffffffffu, s, o);
        float inv = 1.0f / s;
        g_W[base + lane]      = e0 * inv;
        g_W[base + lane + 32] = e1 * inv;
        g_W[base + lane + 64] = e2 * inv;
        g_W[base + lane + 96] = e3 * inv;
    }
}

// ---------------------------------------------------------------------------
// Kernel 2: per (n, f-tile 128), 512 threads: out[c=128][f=128] = sum_m W*X.
// K = m = 128 resident. X kept in natural [m][f] layout; B fragments via
// ldmatrix.trans (no scatter transpose). Warp tile: c 4x32, f 4x32.
// ---------------------------------------------------------------------------
#define K2_S 136
#define K2_WH 0
#define K2_WL 34816
#define K2_TH 69632
#define K2_TL 104448
#define K2_DYN 139264

__global__ __launch_bounds__(512) void k_combine(const float* __restrict__ X,
                                                 float* __restrict__ out) {
    extern __shared__ char sm[];
    const uint32_t sbase = smem_u32(sm);
    const int n = blockIdx.y, fblk = blockIdx.x * 128;
    const int tid = threadIdx.x;
    const int wid = tid >> 5, lane = tid & 31;
    const int wm = wid >> 2, wf = wid & 3;  // c0 = wm*32, f0 = wf*32

    __nv_bfloat16* Wh = (__nv_bfloat16*)(sm + K2_WH);
    __nv_bfloat16* Wl = (__nv_bfloat16*)(sm + K2_WL);
    __nv_bfloat16* Th = (__nv_bfloat16*)(sm + K2_TH);
    __nv_bfloat16* Tl = (__nv_bfloat16*)(sm + K2_TL);

    // W[n]: [c][m] fp32 coalesced -> Wh/Wl [c][m] stride 136
    const float* Wb = g_W + (size_t)n * Cc * Cc;
#pragma unroll
    for (int it = 0; it < 8; it++) {
        int v = tid + it * 512, row = v >> 5, k4 = (v & 31) << 2;
        float4 w = *(const float4*)(Wb + (size_t)row * Cc + k4);
        uint32_t h01, l01, h23, l23;
        split2(w.x, w.y, h01, l01);
        split2(w.z, w.w, h23, l23);
        int e = row * K2_S + k4;
        *(uint2*)(Wh + e) = make_uint2(h01, h23);
        *(uint2*)(Wl + e) = make_uint2(l01, l23);
    }
    // X[n]: [m][f] fp32 coalesced -> Th/Tl natural [m][f] stride 136
    const float* Xb = X + (size_t)n * Cc * Ff + fblk;
#pragma unroll
    for (int it = 0; it < 8; it++) {
        int v = tid + it * 512, m = v >> 5, f4 = (v & 31) << 2;
        float4 x = *(const float4*)(Xb + (size_t)m * Ff + f4);
        uint32_t h01, l01, h23, l23;
        split2(x.x, x.y, h01, l01);
        split2(x.z, x.w, h23, l23);
        int e = m * K2_S + f4;
        *(uint2*)(Th + e) = make_uint2(h01, h23);
        *(uint2*)(Tl + e) = make_uint2(l01, l23);
    }
    __syncthreads();

    float acc[2][4][4];
#pragma unroll
    for (int nb = 0; nb < 2; nb++)
#pragma unroll
        for (int fb = 0; fb < 4; fb++)
#pragma unroll
            for (int j = 0; j < 4; j++) acc[nb][fb][j] = 0.0f;

    const uint32_t wh = sbase + K2_WH, wl = sbase + K2_WL;
    const uint32_t th = sbase + K2_TH, tl = sbase + K2_TL;

#pragma unroll
    for (int ks = 0; ks < 8; ks++) {
        uint32_t wah[2][4], wal[2][4];
#pragma unroll
        for (int nb = 0; nb < 2; nb++) {
            int row  = wm * 32 + nb * 16 + (lane & 15);
            int koff = ks * 16 + ((lane >> 4) << 3);
            uint32_t off = (uint32_t)(row * K2_S + koff) * 2;
            ldm4(wah[nb], wh + off);
            ldm4(wal[nb], wl + off);
        }
        uint32_t bhf[2][4], blf[2][4];
#pragma unroll
        for (int g = 0; g < 2; g++) {
            // trans load from [m=k][f=n]: lanes give k-rows, HW transposes
            int kr = ks * 16 + (((lane >> 3) & 1) << 3) + (lane & 7);
            int nc = wf * 32 + g * 16 + (((lane >> 4) & 1) << 3);
            uint32_t off = (uint32_t)(kr * K2_S + nc) * 2;
            ldm4t(bhf[g], th + off);
            ldm4t(blf[g], tl + off);
        }
#pragma unroll
        for (int nb = 0; nb < 2; nb++)
#pragma unroll
            for (int g = 0; g < 2; g++)
#pragma unroll
                for (int h = 0; h < 2; h++) {
                    int fb = g * 2 + h;
                    mma_bf16(acc[nb][fb], wah[nb], &bhf[g][h * 2]);
                    mma_bf16(acc[nb][fb], wah[nb], &blf[g][h * 2]);
                    mma_bf16(acc[nb][fb], wal[nb], &bhf[g][h * 2]);
                }
    }
    __syncthreads();  // tiles done; reuse smem

    float* S = (float*)sm;
#pragma unroll
    for (int nb = 0; nb < 2; nb++)
#pragma unroll
        for (int fb = 0; fb < 4; fb++) {
            int cc = wm * 32 + nb * 16 + (lane >> 2);
            int f  = wf * 32 + fb * 8 + (lane & 3) * 2;
            *(float2*)&S[cc * 132 + f]       = make_float2(acc[nb][fb][0], acc[nb][fb][1]);
            *(float2*)&S[(cc + 8) * 132 + f] = make_float2(acc[nb][fb][2], acc[nb][fb][3]);
        }
    __syncthreads();

#pragma unroll
    for (int it = 0; it < 8; it++) {
        int v = tid + it * 512, row = v >> 5, f4 = (v & 31) << 2;
        float4 val = *(const float4*)&S[row * 132 + f4];
        *(float4*)(out + ((size_t)n * Cc + row) * Ff + fblk + f4) = val;
    }
}

extern "C" void kernel_launch(void* const* d_in, const int* in_sizes, int n_in,
                              void* d_out, int out_size) {
    const float* X = (const float*)d_in[0];
    const float* A = (const float*)d_in[1];
    float* out = (float*)d_out;
    (void)in_sizes; (void)n_in; (void)out_size;

    cudaFuncSetAttribute(k_scores, cudaFuncAttributeMaxDynamicSharedMemorySize, K1_DYN);
    cudaFuncSetAttribute(k_combine, cudaFuncAttributeMaxDynamicSharedMemorySize, K2_DYN);

    k_scores<<<dim3(128, 2), 512, K1_DYN>>>(X, A);
    k_softmax<<<256, 256>>>();
    k_combine<<<dim3(16, 64), 512, K2_DYN>>>(X, out);
}

// round 7
// speedup vs baseline: 3.1951x; 1.1130x over previous
#include <cuda_runtime.h>
#include <cuda_bf16.h>
#include <cstdint>

#define Nn 64
#define Cc 128
#define Ff 2048

// Scratch: partial scores (2 K-slabs, fp32) + softmax weights
__device__ float g_S[2 * Nn * Cc * Cc];  // 8 MB
__device__ float g_W[Nn * Cc * Cc];      // 4 MB
#define SLAB ((size_t)Nn * Cc * Cc)

// ---------------------------------------------------------------------------
// Portable tensor-core helpers
// ---------------------------------------------------------------------------
__device__ __forceinline__ uint32_t smem_u32(const void* p) {
    uint32_t a;
    asm("{ .reg .u64 t; cvta.to.shared.u64 t, %1; cvt.u32.u64 %0, t; }" : "=r"(a) : "l"(p));
    return a;
}

__device__ __forceinline__ void ldm4(uint32_t* r, uint32_t addr) {
    asm volatile("ldmatrix.sync.aligned.m8n8.x4.shared.b16 {%0,%1,%2,%3}, [%4];"
                 : "=r"(r[0]), "=r"(r[1]), "=r"(r[2]), "=r"(r[3]) : "r"(addr));
}
__device__ __forceinline__ void ldm4t(uint32_t* r, uint32_t addr) {
    asm volatile("ldmatrix.sync.aligned.m8n8.x4.trans.shared.b16 {%0,%1,%2,%3}, [%4];"
                 : "=r"(r[0]), "=r"(r[1]), "=r"(r[2]), "=r"(r[3]) : "r"(addr));
}

__device__ __forceinline__ void mma_bf16(float* d, const uint32_t* a, const uint32_t* b) {
    asm volatile(
        "mma.sync.aligned.m16n8k16.row.col.f32.bf16.bf16.f32 "
        "{%0,%1,%2,%3}, {%4,%5,%6,%7}, {%8,%9}, {%0,%1,%2,%3};"
        : "+f"(d[0]), "+f"(d[1]), "+f"(d[2]), "+f"(d[3])
        : "r"(a[0]), "r"(a[1]), "r"(a[2]), "r"(a[3]), "r"(b[0]), "r"(b[1]));
}

// fp32 pair -> packed bf16x2 (hi) only
__device__ __forceinline__ uint32_t pack2(float a, float b) {
    uint32_t r;
    asm("cvt.rn.bf16x2.f32 %0, %1, %2;" : "=r"(r) : "f"(b), "f"(a));
    return r;
}
// fp32 -> bf16 (hi, lo) split via packed cvt
__device__ __forceinline__ void split2(float a, float b, uint32_t& hi, uint32_t& lo) {
    asm("cvt.rn.bf16x2.f32 %0, %1, %2;" : "=r"(hi) : "f"(b), "f"(a));
    float ha = __uint_as_float(hi << 16);
    float hb = __uint_as_float(hi & 0xffff0000u);
    float ra = a - ha;
    float rb = b - hb;
    asm("cvt.rn.bf16x2.f32 %0, %1, %2;" : "=r"(lo) : "f"(rb), "f"(ra));
}

// ---------------------------------------------------------------------------
// Kernel 1: grid (c=128, kh=2), 512 threads, 2 CTAs/SM.
// S_part[n=64][m=128] = sum_{f in kh-half} X*A. K=1024 in 16 double-buffered
// chunks of 64. X split hi/lo (exact), A bf16-hi only (err ~2e-4 final).
// Row stride 72 elems. Warp tile: n 2x32 (wn), m 8x16 (wm).
// ---------------------------------------------------------------------------
#define K1_SX 72
#define K1_XH 0
#define K1_XL 9216
#define K1_AH 18432
#define K1_BUF 36864
#define K1_DYN (2 * K1_BUF)

__global__ __launch_bounds__(512, 2) void k_scores(const float* __restrict__ X,
                                                   const float* __restrict__ A) {
    extern __shared__ char sm[];
    const uint32_t sbase = smem_u32(sm);
    const int c = blockIdx.x, kh = blockIdx.y;
    const int tid = threadIdx.x;
    const int wid = tid >> 5, lane = tid & 31;
    const int wn = wid & 1, wm = wid >> 1;  // n0 = wn*32, m0 = wm*16

    float acc[2][2][4];
#pragma unroll
    for (int nb = 0; nb < 2; nb++)
#pragma unroll
        for (int mb = 0; mb < 2; mb++)
#pragma unroll
            for (int j = 0; j < 4; j++) acc[nb][mb][j] = 0.0f;

    const float* Ab = A + (size_t)c * Cc * Ff + kh * 1024;  // [m][f]
    const float* Xb = X + (size_t)c * Ff + kh * 1024;       // X[(n*Cc+c)*Ff]

    for (int i = 0; i < 17; i++) {
        if (i < 16) {
            const int f0 = i << 6;
            const int b = i & 1;
            __nv_bfloat16* Xh = (__nv_bfloat16*)(sm + b * K1_BUF + K1_XH);
            __nv_bfloat16* Xl = (__nv_bfloat16*)(sm + b * K1_BUF + K1_XL);
            __nv_bfloat16* Ah = (__nv_bfloat16*)(sm + b * K1_BUF + K1_AH);
#pragma unroll
            for (int it = 0; it < 2; it++) {
                int v = tid + it * 512, n = v >> 4, k4 = (v & 15) << 2;
                float4 x = *(const float4*)(Xb + (size_t)n * Cc * Ff + f0 + k4);
                uint32_t h01, l01, h23, l23;
                split2(x.x, x.y, h01, l01);
                split2(x.z, x.w, h23, l23);
                int e = n * K1_SX + k4;
                *(uint2*)(Xh + e) = make_uint2(h01, h23);
                *(uint2*)(Xl + e) = make_uint2(l01, l23);
            }
#pragma unroll
            for (int it = 0; it < 4; it++) {
                int v = tid + it * 512, m = v >> 4, k4 = (v & 15) << 2;
                float4 a = *(const float4*)(Ab + (size_t)m * Ff + f0 + k4);
                int e = m * K1_SX + k4;
                *(uint2*)(Ah + e) = make_uint2(pack2(a.x, a.y), pack2(a.z, a.w));
            }
        }
        if (i > 0) {
            const int b = (i - 1) & 1;
            const uint32_t xh = sbase + b * K1_BUF + K1_XH;
            const uint32_t xl = sbase + b * K1_BUF + K1_XL;
            const uint32_t ah = sbase + b * K1_BUF + K1_AH;
#pragma unroll
            for (int ks = 0; ks < 4; ks++) {
                uint32_t xah[2][4], xal[2][4];
#pragma unroll
                for (int nb = 0; nb < 2; nb++) {
                    int row  = wn * 32 + nb * 16 + (lane & 15);
                    int koff = ks * 16 + ((lane >> 4) << 3);
                    uint32_t off = (uint32_t)(row * K1_SX + koff) * 2;
                    ldm4(xah[nb], xh + off);
                    ldm4(xal[nb], xl + off);
                }
                uint32_t bhf[4];
                {
                    int row  = wm * 16 + ((lane >> 4) << 3) + (lane & 7);
                    int koff = ks * 16 + (((lane >> 3) & 1) << 3);
                    uint32_t off = (uint32_t)(row * K1_SX + koff) * 2;
                    ldm4(bhf, ah + off);
                }
#pragma unroll
                for (int nb = 0; nb < 2; nb++)
#pragma unroll
                    for (int mb = 0; mb < 2; mb++) {
                        mma_bf16(acc[nb][mb], xah[nb], &bhf[mb * 2]);
                        mma_bf16(acc[nb][mb], xal[nb], &bhf[mb * 2]);
                    }
            }
        }
        __syncthreads();
    }

    // fragments -> smem S[n][m] (stride 132) -> coalesced fp32 stores to slab
    float* S = (float*)sm;
#pragma unroll
    for (int nb = 0; nb < 2; nb++)
#pragma unroll
        for (int mb = 0; mb < 2; mb++) {
            int n = wn * 32 + nb * 16 + (lane >> 2);
            int m = wm * 16 + mb * 8 + (lane & 3) * 2;
            S[n * 132 + m]           = acc[nb][mb][0];
            S[n * 132 + m + 1]       = acc[nb][mb][1];
            S[(n + 8) * 132 + m]     = acc[nb][mb][2];
            S[(n + 8) * 132 + m + 1] = acc[nb][mb][3];
        }
    __syncthreads();

    float* slab = g_S + (size_t)kh * SLAB;
#pragma unroll
    for (int it = 0; it < 4; it++) {
        int v = tid + it * 512, n = v >> 5, m4 = (v & 31) << 2;
        float4 val = *(const float4*)&S[n * 132 + m4];
        *(float4*)(slab + ((size_t)n * Cc + c) * Cc + m4) = val;
    }
}

// ---------------------------------------------------------------------------
// Softmax: combine the two K-slabs, softmax over m (128), write g_W.
// ---------------------------------------------------------------------------
__global__ __launch_bounds__(256) void k_softmax() {
    const int tid = threadIdx.x, wid = tid >> 5, lane = tid & 31;
    const int r0 = blockIdx.x * 32 + wid * 4;
#pragma unroll
    for (int j = 0; j < 4; j++) {
        int r = r0 + j;
        size_t base = (size_t)r * Cc;
        float v0 = g_S[base + lane]      + g_S[SLAB + base + lane];
        float v1 = g_S[base + lane + 32] + g_S[SLAB + base + lane + 32];
        float v2 = g_S[base + lane + 64] + g_S[SLAB + base + lane + 64];
        float v3 = g_S[base + lane + 96] + g_S[SLAB + base + lane + 96];
        float mx = fmaxf(fmaxf(v0, v1), fmaxf(v2, v3));
#pragma unroll
        for (int o = 16; o > 0; o >>= 1)
            mx = fmaxf(mx, __shfl_xor_sync(0xffffffffu, mx, o));
        float e0 = __expf(v0 - mx);
        float e1 = __expf(v1 - mx);
        float e2 = __expf(v2 - mx);
        float e3 = __expf(v3 - mx);
        float s = e0 + e1 + e2 + e3;
#pragma unroll
        for (int o = 16; o > 0; o >>= 1)
            s += __shfl_xor_sync(0xffffffffu, s, o);
        float inv = 1.0f / s;
        g_W[base + lane]      = e0 * inv;
        g_W[base + lane + 32] = e1 * inv;
        g_W[base + lane + 64] = e2 * inv;
        g_W[base + lane + 96] = e3 * inv;
    }
}

// ---------------------------------------------------------------------------
// Kernel 2: per (n, f-tile 64), 512 threads, 2 CTAs/SM:
// out[c=128][f=64] = sum_m W[n,c,m]*X[n,m,f]. K = m = 128 resident.
// W split hi/lo (stride 136); X natural [m][f] hi/lo (stride 72), B frags via
// ldmatrix.trans. Warp tile: c 4x32 (wm), f 4x16 (wf). Full 3-product split.
// ---------------------------------------------------------------------------
#define K2_SW 136
#define K2_ST 72
#define K2_WH 0
#define K2_WL 34816
#define K2_TH 69632
#define K2_TL 88064
#define K2_DYN 106496

__global__ __launch_bounds__(512, 2) void k_combine(const float* __restrict__ X,
                                                    float* __restrict__ out) {
    extern __shared__ char sm[];
    const uint32_t sbase = smem_u32(sm);
    const int n = blockIdx.y, fblk = blockIdx.x * 64;
    const int tid = threadIdx.x;
    const int wid = tid >> 5, lane = tid & 31;
    const int wm = wid >> 2, wf = wid & 3;  // c0 = wm*32, f0 = wf*16

    __nv_bfloat16* Wh = (__nv_bfloat16*)(sm + K2_WH);
    __nv_bfloat16* Wl = (__nv_bfloat16*)(sm + K2_WL);
    __nv_bfloat16* Th = (__nv_bfloat16*)(sm + K2_TH);
    __nv_bfloat16* Tl = (__nv_bfloat16*)(sm + K2_TL);

    // W[n]: [c][m] fp32 coalesced -> Wh/Wl [c][m] stride 136
    const float* Wb = g_W + (size_t)n * Cc * Cc;
#pragma unroll
    for (int it = 0; it < 8; it++) {
        int v = tid + it * 512, row = v >> 5, k4 = (v & 31) << 2;
        float4 w = *(const float4*)(Wb + (size_t)row * Cc + k4);
        uint32_t h01, l01, h23, l23;
        split2(w.x, w.y, h01, l01);
        split2(w.z, w.w, h23, l23);
        int e = row * K2_SW + k4;
        *(uint2*)(Wh + e) = make_uint2(h01, h23);
        *(uint2*)(Wl + e) = make_uint2(l01, l23);
    }
    // X[n]: [m][f-tile 64] fp32 -> Th/Tl natural [m][f] stride 72
    const float* Xb = X + (size_t)n * Cc * Ff + fblk;
#pragma unroll
    for (int it = 0; it < 4; it++) {
        int v = tid + it * 512, m = v >> 4, f4 = (v & 15) << 2;
        float4 x = *(const float4*)(Xb + (size_t)m * Ff + f4);
        uint32_t h01, l01, h23, l23;
        split2(x.x, x.y, h01, l01);
        split2(x.z, x.w, h23, l23);
        int e = m * K2_ST + f4;
        *(uint2*)(Th + e) = make_uint2(h01, h23);
        *(uint2*)(Tl + e) = make_uint2(l01, l23);
    }
    __syncthreads();

    float acc[2][2][4];
#pragma unroll
    for (int nb = 0; nb < 2; nb++)
#pragma unroll
        for (int fb = 0; fb < 2; fb++)
#pragma unroll
            for (int j = 0; j < 4; j++) acc[nb][fb][j] = 0.0f;

    const uint32_t wh = sbase + K2_WH, wl = sbase + K2_WL;
    const uint32_t th = sbase + K2_TH, tl = sbase + K2_TL;

#pragma unroll
    for (int ks = 0; ks < 8; ks++) {
        uint32_t wah[2][4], wal[2][4];
#pragma unroll
        for (int nb = 0; nb < 2; nb++) {
            int row  = wm * 32 + nb * 16 + (lane & 15);
            int koff = ks * 16 + ((lane >> 4) << 3);
            uint32_t off = (uint32_t)(row * K2_SW + koff) * 2;
            ldm4(wah[nb], wh + off);
            ldm4(wal[nb], wl + off);
        }
        uint32_t bhf[4], blf[4];
        {
            int kr = ks * 16 + (((lane >> 3) & 1) << 3) + (lane & 7);
            int nc = wf * 16 + ((lane >> 4) << 3);
            uint32_t off = (uint32_t)(kr * K2_ST + nc) * 2;
            ldm4t(bhf, th + off);
            ldm4t(blf, tl + off);
        }
#pragma unroll
        for (int nb = 0; nb < 2; nb++)
#pragma unroll
            for (int h = 0; h < 2; h++) {
                mma_bf16(acc[nb][h], wah[nb], &bhf[h * 2]);
                mma_bf16(acc[nb][h], wah[nb], &blf[h * 2]);
                mma_bf16(acc[nb][h], wal[nb], &bhf[h * 2]);
            }
    }
    __syncthreads();  // tiles done; reuse smem

    float* S = (float*)sm;  // [c=128][f 64 pad 68]
#pragma unroll
    for (int nb = 0; nb < 2; nb++)
#pragma unroll
        for (int fb = 0; fb < 2; fb++) {
            int cc = wm * 32 + nb * 16 + (lane >> 2);
            int f  = wf * 16 + fb * 8 + (lane & 3) * 2;
            *(float2*)&S[cc * 68 + f]       = make_float2(acc[nb][fb][0], acc[nb][fb][1]);
            *(float2*)&S[(cc + 8) * 68 + f] = make_float2(acc[nb][fb][2], acc[nb][fb][3]);
        }
    __syncthreads();

#pragma unroll
    for (int it = 0; it < 4; it++) {
        int v = tid + it * 512, row = v >> 4, f4 = (v & 15) << 2;
        float4 val = *(const float4*)&S[row * 68 + f4];
        *(float4*)(out + ((size_t)n * Cc + row) * Ff + fblk + f4) = val;
    }
}

extern "C" void kernel_launch(void* const* d_in, const int* in_sizes, int n_in,
                              void* d_out, int out_size) {
    const float* X = (const float*)d_in[0];
    const float* A = (const float*)d_in[1];
    float* out = (float*)d_out;
    (void)in_sizes; (void)n_in; (void)out_size;

    cudaFuncSetAttribute(k_scores, cudaFuncAttributeMaxDynamicSharedMemorySize, K1_DYN);
    cudaFuncSetAttribute(k_combine, cudaFuncAttributeMaxDynamicSharedMemorySize, K2_DYN);

    k_scores<<<dim3(128, 2), 512, K1_DYN>>>(X, A);
    k_softmax<<<256, 256>>>();
    k_combine<<<dim3(32, 64), 512, K2_DYN>>>(X, out);
}

// round 8
// speedup vs baseline: 3.4224x; 1.0712x over previous
#include <cuda_runtime.h>
#include <cuda_bf16.h>
#include <cstdint>

#define Nn 64
#define Cc 128
#define Ff 2048

// Scratch: partial scores (2 K-slabs, fp32) + softmax weights as bf16 hi/lo
__device__ float g_S[2 * Nn * Cc * Cc];            // 8 MB
__device__ __nv_bfloat16 g_Wh[Nn * Cc * Cc];       // 2 MB
__device__ __nv_bfloat16 g_Wl[Nn * Cc * Cc];       // 2 MB
#define SLAB ((size_t)Nn * Cc * Cc)

// ---------------------------------------------------------------------------
// Portable tensor-core helpers
// ---------------------------------------------------------------------------
__device__ __forceinline__ uint32_t smem_u32(const void* p) {
    uint32_t a;
    asm("{ .reg .u64 t; cvta.to.shared.u64 t, %1; cvt.u32.u64 %0, t; }" : "=r"(a) : "l"(p));
    return a;
}

__device__ __forceinline__ void ldm4(uint32_t* r, uint32_t addr) {
    asm volatile("ldmatrix.sync.aligned.m8n8.x4.shared.b16 {%0,%1,%2,%3}, [%4];"
                 : "=r"(r[0]), "=r"(r[1]), "=r"(r[2]), "=r"(r[3]) : "r"(addr));
}
__device__ __forceinline__ void ldm4t(uint32_t* r, uint32_t addr) {
    asm volatile("ldmatrix.sync.aligned.m8n8.x4.trans.shared.b16 {%0,%1,%2,%3}, [%4];"
                 : "=r"(r[0]), "=r"(r[1]), "=r"(r[2]), "=r"(r[3]) : "r"(addr));
}

__device__ __forceinline__ void mma_bf16(float* d, const uint32_t* a, const uint32_t* b) {
    asm volatile(
        "mma.sync.aligned.m16n8k16.row.col.f32.bf16.bf16.f32 "
        "{%0,%1,%2,%3}, {%4,%5,%6,%7}, {%8,%9}, {%0,%1,%2,%3};"
        : "+f"(d[0]), "+f"(d[1]), "+f"(d[2]), "+f"(d[3])
        : "r"(a[0]), "r"(a[1]), "r"(a[2]), "r"(a[3]), "r"(b[0]), "r"(b[1]));
}

#define BAR_SYNC(id) asm volatile("bar.sync %0, 512;" :: "r"(id) : "memory")
#define BAR_ARRIVE(id) asm volatile("bar.arrive %0, 512;" :: "r"(id) : "memory")

// fp32 pair -> packed bf16x2 (hi) only
__device__ __forceinline__ uint32_t pack2(float a, float b) {
    uint32_t r;
    asm("cvt.rn.bf16x2.f32 %0, %1, %2;" : "=r"(r) : "f"(b), "f"(a));
    return r;
}
// fp32 -> bf16 (hi, lo) split via packed cvt
__device__ __forceinline__ void split2(float a, float b, uint32_t& hi, uint32_t& lo) {
    asm("cvt.rn.bf16x2.f32 %0, %1, %2;" : "=r"(hi) : "f"(b), "f"(a));
    float ha = __uint_as_float(hi << 16);
    float hb = __uint_as_float(hi & 0xffff0000u);
    float ra = a - ha;
    float rb = b - hb;
    asm("cvt.rn.bf16x2.f32 %0, %1, %2;" : "=r"(lo) : "f"(rb), "f"(ra));
}

// ---------------------------------------------------------------------------
// Kernel 1: grid (c=128, kh=2), 512 threads, 2 CTAs/SM, warp-specialized:
// warps 0-7 consume (MMA), warps 8-15 produce (LDG->cvt->STS).
// S_part[n=64][m=128] = sum_{f half} X*A. K=1024, 16 double-buffered chunks
// of 64. X split hi/lo (exact), A bf16-hi. Named barriers: full/empty per buf.
// Consumer warp tile: n 2x32 (wn), m 4x32 (wm).
// ---------------------------------------------------------------------------
#define K1_SX 72
#define K1_XH 0
#define K1_XL 9216
#define K1_AH 18432
#define K1_BUF 36864
#define K1_DYN (2 * K1_BUF)

__global__ __launch_bounds__(512, 2) void k_scores(const float* __restrict__ X,
                                                   const float* __restrict__ A) {
    extern __shared__ char sm[];
    const uint32_t sbase = smem_u32(sm);
    const int c = blockIdx.x, kh = blockIdx.y;
    const int tid = threadIdx.x;
    const int wid = tid >> 5, lane = tid & 31;

    const float* Ab = A + (size_t)c * Cc * Ff + kh * 1024;  // [m][f]
    const float* Xb = X + (size_t)c * Ff + kh * 1024;       // X[(n*Cc+c)*Ff]

    float acc[2][4][4];
#pragma unroll
    for (int nb = 0; nb < 2; nb++)
#pragma unroll
        for (int fb = 0; fb < 4; fb++)
#pragma unroll
            for (int j = 0; j < 4; j++) acc[nb][fb][j] = 0.0f;

    if (wid >= 8) {
        // ---------------- producers ----------------
        const int ptid = tid - 256;
        for (int i = 0; i < 16; i++) {
            const int b = i & 1;
            if (i >= 2) BAR_SYNC(3 + b);
            const int f0 = i << 6;
            __nv_bfloat16* Xh = (__nv_bfloat16*)(sm + b * K1_BUF + K1_XH);
            __nv_bfloat16* Xl = (__nv_bfloat16*)(sm + b * K1_BUF + K1_XL);
            __nv_bfloat16* Ah = (__nv_bfloat16*)(sm + b * K1_BUF + K1_AH);

            float4 xv[4], av0[4], av1[4];
#pragma unroll
            for (int it = 0; it < 4; it++) {
                int v = ptid + it * 256, n = v >> 4, k4 = (v & 15) << 2;
                xv[it] = *(const float4*)(Xb + (size_t)n * Cc * Ff + f0 + k4);
            }
#pragma unroll
            for (int it = 0; it < 4; it++) {
                int v = ptid + it * 256, m = v >> 4, k4 = (v & 15) << 2;
                av0[it] = *(const float4*)(Ab + (size_t)m * Ff + f0 + k4);
            }
#pragma unroll
            for (int it = 0; it < 4; it++) {
                int v = ptid + it * 256 + 1024, m = v >> 4, k4 = (v & 15) << 2;
                av1[it] = *(const float4*)(Ab + (size_t)m * Ff + f0 + k4);
            }
#pragma unroll
            for (int it = 0; it < 4; it++) {
                int v = ptid + it * 256, n = v >> 4, k4 = (v & 15) << 2;
                uint32_t h01, l01, h23, l23;
                split2(xv[it].x, xv[it].y, h01, l01);
                split2(xv[it].z, xv[it].w, h23, l23);
                int e = n * K1_SX + k4;
                *(uint2*)(Xh + e) = make_uint2(h01, h23);
                *(uint2*)(Xl + e) = make_uint2(l01, l23);
            }
#pragma unroll
            for (int it = 0; it < 4; it++) {
                int v = ptid + it * 256, m = v >> 4, k4 = (v & 15) << 2;
                *(uint2*)(Ah + m * K1_SX + k4) =
                    make_uint2(pack2(av0[it].x, av0[it].y), pack2(av0[it].z, av0[it].w));
            }
#pragma unroll
            for (int it = 0; it < 4; it++) {
                int v = ptid + it * 256 + 1024, m = v >> 4, k4 = (v & 15) << 2;
                *(uint2*)(Ah + m * K1_SX + k4) =
                    make_uint2(pack2(av1[it].x, av1[it].y), pack2(av1[it].z, av1[it].w));
            }
            BAR_ARRIVE(1 + b);
        }
    } else {
        // ---------------- consumers ----------------
        const int wn = wid & 1, wm = wid >> 1;  // n0 = wn*32, m0 = wm*32
        for (int i = 0; i < 16; i++) {
            const int b = i & 1;
            BAR_SYNC(1 + b);
            const uint32_t xh = sbase + b * K1_BUF + K1_XH;
            const uint32_t xl = sbase + b * K1_BUF + K1_XL;
            const uint32_t ah = sbase + b * K1_BUF + K1_AH;
#pragma unroll
            for (int ks = 0; ks < 4; ks++) {
                uint32_t xah[2][4], xal[2][4];
#pragma unroll
                for (int nb = 0; nb < 2; nb++) {
                    int row  = wn * 32 + nb * 16 + (lane & 15);
                    int koff = ks * 16 + ((lane >> 4) << 3);
                    uint32_t off = (uint32_t)(row * K1_SX + koff) * 2;
                    ldm4(xah[nb], xh + off);
                    ldm4(xal[nb], xl + off);
                }
#pragma unroll
                for (int g = 0; g < 2; g++) {
                    uint32_t af[4];
                    int row  = wm * 32 + g * 16 + ((lane >> 4) << 3) + (lane & 7);
                    int koff = ks * 16 + (((lane >> 3) & 1) << 3);
                    ldm4(af, ah + (uint32_t)(row * K1_SX + koff) * 2);
#pragma unroll
                    for (int nb = 0; nb < 2; nb++)
#pragma unroll
                        for (int h = 0; h < 2; h++) {
                            mma_bf16(acc[nb][g * 2 + h], xah[nb], &af[h * 2]);
                            mma_bf16(acc[nb][g * 2 + h], xal[nb], &af[h * 2]);
                        }
                }
            }
            BAR_ARRIVE(3 + b);
        }
    }

    // Consumers write S[n][m] (stride 132) into buf0 region; everyone syncs.
    float* S = (float*)sm;
    if (wid < 8) {
        const int wn = wid & 1, wm = wid >> 1;
#pragma unroll
        for (int nb = 0; nb < 2; nb++)
#pragma unroll
            for (int fb = 0; fb < 4; fb++) {
                int n = wn * 32 + nb * 16 + (lane >> 2);
                int m = wm * 32 + fb * 8 + (lane & 3) * 2;
                S[n * 132 + m]           = acc[nb][fb][0];
                S[n * 132 + m + 1]       = acc[nb][fb][1];
                S[(n + 8) * 132 + m]     = acc[nb][fb][2];
                S[(n + 8) * 132 + m + 1] = acc[nb][fb][3];
            }
    }
    __syncthreads();

    float* slab = g_S + (size_t)kh * SLAB;
#pragma unroll
    for (int it = 0; it < 4; it++) {
        int v = tid + it * 512, n = v >> 5, m4 = (v & 31) << 2;
        float4 val = *(const float4*)&S[n * 132 + m4];
        *(float4*)(slab + ((size_t)n * Cc + c) * Cc + m4) = val;
    }
}

// ---------------------------------------------------------------------------
// Softmax: combine the two K-slabs, softmax over m, emit bf16 hi/lo weights.
// ---------------------------------------------------------------------------
__global__ __launch_bounds__(256) void k_softmax() {
    const int tid = threadIdx.x, wid = tid >> 5, lane = tid & 31;
    const int r0 = blockIdx.x * 32 + wid * 4;
#pragma unroll
    for (int j = 0; j < 4; j++) {
        int r = r0 + j;
        size_t base = (size_t)r * Cc;
        float v0 = g_S[base + lane]      + g_S[SLAB + base + lane];
        float v1 = g_S[base + lane + 32] + g_S[SLAB + base + lane + 32];
        float v2 = g_S[base + lane + 64] + g_S[SLAB + base + lane + 64];
        float v3 = g_S[base + lane + 96] + g_S[SLAB + base + lane + 96];
        float mx = fmaxf(fmaxf(v0, v1), fmaxf(v2, v3));
#pragma unroll
        for (int o = 16; o > 0; o >>= 1)
            mx = fmaxf(mx, __shfl_xor_sync(0xffffffffu, mx, o));
        float e0 = __expf(v0 - mx);
        float e1 = __expf(v1 - mx);
        float e2 = __expf(v2 - mx);
        float e3 = __expf(v3 - mx);
        float s = e0 + e1 + e2 + e3;
#pragma unroll
        for (int o = 16; o > 0; o >>= 1)
            s += __shfl_xor_sync(0xffffffffu, s, o);
        float inv = 1.0f / s;
        float w[4] = {e0 * inv, e1 * inv, e2 * inv, e3 * inv};
#pragma unroll
        for (int q = 0; q < 4; q++) {
            __nv_bfloat16 h = __float2bfloat16(w[q]);
            __nv_bfloat16 l = __float2bfloat16(w[q] - __bfloat162float(h));
            g_Wh[base + lane + q * 32] = h;
            g_Wl[base + lane + q * 32] = l;
        }
    }
}

// ---------------------------------------------------------------------------
// Kernel 2: per (n, f-tile 64), 512 threads, 2 CTAs/SM:
// out[c=128][f=64] = sum_m W[n,c,m]*X[n,m,f]. K = m = 128 resident.
// W loaded pre-split bf16 (pure copy); X natural [m][f] hi/lo, B frags via
// ldmatrix.trans. Warp tile: c 4x32 (wm), f 4x16 (wf). Full 3-product split.
// ---------------------------------------------------------------------------
#define K2_SW 136
#define K2_ST 72
#define K2_WH 0
#define K2_WL 34816
#define K2_TH 69632
#define K2_TL 88064
#define K2_DYN 106496

__global__ __launch_bounds__(512, 2) void k_combine(const float* __restrict__ X,
                                                    float* __restrict__ out) {
    extern __shared__ char sm[];
    const uint32_t sbase = smem_u32(sm);
    const int n = blockIdx.y, fblk = blockIdx.x * 64;
    const int tid = threadIdx.x;
    const int wid = tid >> 5, lane = tid & 31;
    const int wm = wid >> 2, wf = wid & 3;  // c0 = wm*32, f0 = wf*16

    __nv_bfloat16* Wh = (__nv_bfloat16*)(sm + K2_WH);
    __nv_bfloat16* Wl = (__nv_bfloat16*)(sm + K2_WL);
    __nv_bfloat16* Th = (__nv_bfloat16*)(sm + K2_TH);
    __nv_bfloat16* Tl = (__nv_bfloat16*)(sm + K2_TL);

    // W[n]: pre-split bf16, straight 16B copies into stride-136 rows
    const __nv_bfloat16* WhG = g_Wh + (size_t)n * Cc * Cc;
    const __nv_bfloat16* WlG = g_Wl + (size_t)n * Cc * Cc;
#pragma unroll
    for (int it = 0; it < 4; it++) {
        int v = tid + it * 512, row = v >> 4, c8 = (v & 15) << 3;
        *(uint4*)(Wh + row * K2_SW + c8) = *(const uint4*)(WhG + row * Cc + c8);
        *(uint4*)(Wl + row * K2_SW + c8) = *(const uint4*)(WlG + row * Cc + c8);
    }
    // X[n]: [m][f-tile 64] fp32 -> Th/Tl natural [m][f] stride 72
    const float* Xb = X + (size_t)n * Cc * Ff + fblk;
#pragma unroll
    for (int it = 0; it < 4; it++) {
        int v = tid + it * 512, m = v >> 4, f4 = (v & 15) << 2;
        float4 x = *(const float4*)(Xb + (size_t)m * Ff + f4);
        uint32_t h01, l01, h23, l23;
        split2(x.x, x.y, h01, l01);
        split2(x.z, x.w, h23, l23);
        int e = m * K2_ST + f4;
        *(uint2*)(Th + e) = make_uint2(h01, h23);
        *(uint2*)(Tl + e) = make_uint2(l01, l23);
    }
    __syncthreads();

    float acc[2][2][4];
#pragma unroll
    for (int nb = 0; nb < 2; nb++)
#pragma unroll
        for (int fb = 0; fb < 2; fb++)
#pragma unroll
            for (int j = 0; j < 4; j++) acc[nb][fb][j] = 0.0f;

    const uint32_t wh = sbase + K2_WH, wl = sbase + K2_WL;
    const uint32_t th = sbase + K2_TH, tl = sbase + K2_TL;

#pragma unroll
    for (int ks = 0; ks < 8; ks++) {
        uint32_t wah[2][4], wal[2][4];
#pragma unroll
        for (int nb = 0; nb < 2; nb++) {
            int row  = wm * 32 + nb * 16 + (lane & 15);
            int koff = ks * 16 + ((lane >> 4) << 3);
            uint32_t off = (uint32_t)(row * K2_SW + koff) * 2;
            ldm4(wah[nb], wh + off);
            ldm4(wal[nb], wl + off);
        }
        uint32_t bhf[4], blf[4];
        {
            int kr = ks * 16 + (((lane >> 3) & 1) << 3) + (lane & 7);
            int nc = wf * 16 + ((lane >> 4) << 3);
            uint32_t off = (uint32_t)(kr * K2_ST + nc) * 2;
            ldm4t(bhf, th + off);
            ldm4t(blf, tl + off);
        }
#pragma unroll
        for (int nb = 0; nb < 2; nb++)
#pragma unroll
            for (int h = 0; h < 2; h++) {
                mma_bf16(acc[nb][h], wah[nb], &bhf[h * 2]);
                mma_bf16(acc[nb][h], wah[nb], &blf[h * 2]);
                mma_bf16(acc[nb][h], wal[nb], &bhf[h * 2]);
            }
    }
    __syncthreads();  // tiles done; reuse smem

    float* S = (float*)sm;  // [c=128][f 64 pad 68]
#pragma unroll
    for (int nb = 0; nb < 2; nb++)
#pragma unroll
        for (int fb = 0; fb < 2; fb++) {
            int cc = wm * 32 + nb * 16 + (lane >> 2);
            int f  = wf * 16 + fb * 8 + (lane & 3) * 2;
            *(float2*)&S[cc * 68 + f]       = make_float2(acc[nb][fb][0], acc[nb][fb][1]);
            *(float2*)&S[(cc + 8) * 68 + f] = make_float2(acc[nb][fb][2], acc[nb][fb][3]);
        }
    __syncthreads();

#pragma unroll
    for (int it = 0; it < 4; it++) {
        int v = tid + it * 512, row = v >> 4, f4 = (v & 15) << 2;
        float4 val = *(const float4*)&S[row * 68 + f4];
        *(float4*)(out + ((size_t)n * Cc + row) * Ff + fblk + f4) = val;
    }
}

extern "C" void kernel_launch(void* const* d_in, const int* in_sizes, int n_in,
                              void* d_out, int out_size) {
    const float* X = (const float*)d_in[0];
    const float* A = (const float*)d_in[1];
    float* out = (float*)d_out;
    (void)in_sizes; (void)n_in; (void)out_size;

    cudaFuncSetAttribute(k_scores, cudaFuncAttributeMaxDynamicSharedMemorySize, K1_DYN);
    cudaFuncSetAttribute(k_combine, cudaFuncAttributeMaxDynamicSharedMemorySize, K2_DYN);

    k_scores<<<dim3(128, 2), 512, K1_DYN>>>(X, A);
    k_softmax<<<256, 256>>>();
    k_combine<<<dim3(32, 64), 512, K2_DYN>>>(X, out);
}

// round 9
// speedup vs baseline: 3.4904x; 1.0199x over previous
#include <cuda_runtime.h>
#include <cuda_bf16.h>
#include <cstdint>

#define Nn 64
#define Cc 128
#define Ff 2048

// Scratch: partial scores (2 K-slabs, fp32) + softmax weights as bf16 hi/lo
__device__ float g_S[2 * Nn * Cc * Cc];            // 8 MB
__device__ __nv_bfloat16 g_Wh[Nn * Cc * Cc];       // 2 MB
__device__ __nv_bfloat16 g_Wl[Nn * Cc * Cc];       // 2 MB
#define SLAB ((size_t)Nn * Cc * Cc)

// ---------------------------------------------------------------------------
// Portable tensor-core helpers
// ---------------------------------------------------------------------------
__device__ __forceinline__ uint32_t smem_u32(const void* p) {
    uint32_t a;
    asm("{ .reg .u64 t; cvta.to.shared.u64 t, %1; cvt.u32.u64 %0, t; }" : "=r"(a) : "l"(p));
    return a;
}

__device__ __forceinline__ void ldm4(uint32_t* r, uint32_t addr) {
    asm volatile("ldmatrix.sync.aligned.m8n8.x4.shared.b16 {%0,%1,%2,%3}, [%4];"
                 : "=r"(r[0]), "=r"(r[1]), "=r"(r[2]), "=r"(r[3]) : "r"(addr));
}
__device__ __forceinline__ void ldm4t(uint32_t* r, uint32_t addr) {
    asm volatile("ldmatrix.sync.aligned.m8n8.x4.trans.shared.b16 {%0,%1,%2,%3}, [%4];"
                 : "=r"(r[0]), "=r"(r[1]), "=r"(r[2]), "=r"(r[3]) : "r"(addr));
}

__device__ __forceinline__ void mma_bf16(float* d, const uint32_t* a, const uint32_t* b) {
    asm volatile(
        "mma.sync.aligned.m16n8k16.row.col.f32.bf16.bf16.f32 "
        "{%0,%1,%2,%3}, {%4,%5,%6,%7}, {%8,%9}, {%0,%1,%2,%3};"
        : "+f"(d[0]), "+f"(d[1]), "+f"(d[2]), "+f"(d[3])
        : "r"(a[0]), "r"(a[1]), "r"(a[2]), "r"(a[3]), "r"(b[0]), "r"(b[1]));
}

#define BAR_SYNC(id) asm volatile("bar.sync %0, 512;" :: "r"(id) : "memory")
#define BAR_ARRIVE(id) asm volatile("bar.arrive %0, 512;" :: "r"(id) : "memory")

__device__ __forceinline__ void cp_async16(uint32_t dst, const void* src) {
    asm volatile("cp.async.ca.shared.global [%0], [%1], 16;" :: "r"(dst), "l"(src) : "memory");
}
#define CP_COMMIT() asm volatile("cp.async.commit_group;" ::: "memory")
#define CP_WAIT0()  asm volatile("cp.async.wait_group 0;" ::: "memory")

// fp32 pair -> packed bf16x2 (hi) only
__device__ __forceinline__ uint32_t pack2(float a, float b) {
    uint32_t r;
    asm("cvt.rn.bf16x2.f32 %0, %1, %2;" : "=r"(r) : "f"(b), "f"(a));
    return r;
}
// fp32 -> bf16 (hi, lo) split via packed cvt
__device__ __forceinline__ void split2(float a, float b, uint32_t& hi, uint32_t& lo) {
    asm("cvt.rn.bf16x2.f32 %0, %1, %2;" : "=r"(hi) : "f"(b), "f"(a));
    float ha = __uint_as_float(hi << 16);
    float hb = __uint_as_float(hi & 0xffff0000u);
    float ra = a - ha;
    float rb = b - hb;
    asm("cvt.rn.bf16x2.f32 %0, %1, %2;" : "=r"(lo) : "f"(rb), "f"(ra));
}

// ---------------------------------------------------------------------------
// Kernel 1: grid (c=128, kh=2), 512 threads, 2 CTAs/SM, warp-specialized:
// warps 0-7 consume (MMA), warps 8-15 produce (LDG->cvt->STS).
// S_part[n=64][m=128] = sum_{f half} X*A. K=1024, 16 double-buffered chunks
// of 64. Both X and A bf16-hi only (err ~3e-4 final, under 1e-3 gate).
// Consumer warp tile: n 2x32 (wn), m 4x32 (wm).
// ---------------------------------------------------------------------------
#define K1_SX 72
#define K1_XH 0
#define K1_AH 9216
#define K1_BUF 27648
#define K1_DYN (2 * K1_BUF)

__global__ __launch_bounds__(512, 2) void k_scores(const float* __restrict__ X,
                                                   const float* __restrict__ A) {
    extern __shared__ char sm[];
    const uint32_t sbase = smem_u32(sm);
    const int c = blockIdx.x, kh = blockIdx.y;
    const int tid = threadIdx.x;
    const int wid = tid >> 5, lane = tid & 31;

    const float* Ab = A + (size_t)c * Cc * Ff + kh * 1024;  // [m][f]
    const float* Xb = X + (size_t)c * Ff + kh * 1024;       // X[(n*Cc+c)*Ff]

    float acc[2][4][4];
#pragma unroll
    for (int nb = 0; nb < 2; nb++)
#pragma unroll
        for (int fb = 0; fb < 4; fb++)
#pragma unroll
            for (int j = 0; j < 4; j++) acc[nb][fb][j] = 0.0f;

    if (wid >= 8) {
        // ---------------- producers ----------------
        const int ptid = tid - 256;
        for (int i = 0; i < 16; i++) {
            const int b = i & 1;
            if (i >= 2) BAR_SYNC(3 + b);
            const int f0 = i << 6;
            __nv_bfloat16* Xh = (__nv_bfloat16*)(sm + b * K1_BUF + K1_XH);
            __nv_bfloat16* Ah = (__nv_bfloat16*)(sm + b * K1_BUF + K1_AH);

            float4 xv[4], av0[4], av1[4];
#pragma unroll
            for (int it = 0; it < 4; it++) {
                int v = ptid + it * 256, n = v >> 4, k4 = (v & 15) << 2;
                xv[it] = *(const float4*)(Xb + (size_t)n * Cc * Ff + f0 + k4);
            }
#pragma unroll
            for (int it = 0; it < 4; it++) {
                int v = ptid + it * 256, m = v >> 4, k4 = (v & 15) << 2;
                av0[it] = *(const float4*)(Ab + (size_t)m * Ff + f0 + k4);
            }
#pragma unroll
            for (int it = 0; it < 4; it++) {
                int v = ptid + it * 256 + 1024, m = v >> 4, k4 = (v & 15) << 2;
                av1[it] = *(const float4*)(Ab + (size_t)m * Ff + f0 + k4);
            }
#pragma unroll
            for (int it = 0; it < 4; it++) {
                int v = ptid + it * 256, n = v >> 4, k4 = (v & 15) << 2;
                *(uint2*)(Xh + n * K1_SX + k4) =
                    make_uint2(pack2(xv[it].x, xv[it].y), pack2(xv[it].z, xv[it].w));
            }
#pragma unroll
            for (int it = 0; it < 4; it++) {
                int v = ptid + it * 256, m = v >> 4, k4 = (v & 15) << 2;
                *(uint2*)(Ah + m * K1_SX + k4) =
                    make_uint2(pack2(av0[it].x, av0[it].y), pack2(av0[it].z, av0[it].w));
            }
#pragma unroll
            for (int it = 0; it < 4; it++) {
                int v = ptid + it * 256 + 1024, m = v >> 4, k4 = (v & 15) << 2;
                *(uint2*)(Ah + m * K1_SX + k4) =
                    make_uint2(pack2(av1[it].x, av1[it].y), pack2(av1[it].z, av1[it].w));
            }
            BAR_ARRIVE(1 + b);
        }
    } else {
        // ---------------- consumers ----------------
        const int wn = wid & 1, wm = wid >> 1;  // n0 = wn*32, m0 = wm*32
        for (int i = 0; i < 16; i++) {
            const int b = i & 1;
            BAR_SYNC(1 + b);
            const uint32_t xh = sbase + b * K1_BUF + K1_XH;
            const uint32_t ah = sbase + b * K1_BUF + K1_AH;
#pragma unroll
            for (int ks = 0; ks < 4; ks++) {
                uint32_t xah[2][4];
#pragma unroll
                for (int nb = 0; nb < 2; nb++) {
                    int row  = wn * 32 + nb * 16 + (lane & 15);
                    int koff = ks * 16 + ((lane >> 4) << 3);
                    ldm4(xah[nb], xh + (uint32_t)(row * K1_SX + koff) * 2);
                }
#pragma unroll
                for (int g = 0; g < 2; g++) {
                    uint32_t af[4];
                    int row  = wm * 32 + g * 16 + ((lane >> 4) << 3) + (lane & 7);
                    int koff = ks * 16 + (((lane >> 3) & 1) << 3);
                    ldm4(af, ah + (uint32_t)(row * K1_SX + koff) * 2);
#pragma unroll
                    for (int nb = 0; nb < 2; nb++)
#pragma unroll
                        for (int h = 0; h < 2; h++)
                            mma_bf16(acc[nb][g * 2 + h], xah[nb], &af[h * 2]);
                }
            }
            BAR_ARRIVE(3 + b);
        }
    }

    // Consumers write S[n][m] (stride 132); everyone syncs, then store slab.
    float* S = (float*)sm;
    if (wid < 8) {
        const int wn = wid & 1, wm = wid >> 1;
#pragma unroll
        for (int nb = 0; nb < 2; nb++)
#pragma unroll
            for (int fb = 0; fb < 4; fb++) {
                int n = wn * 32 + nb * 16 + (lane >> 2);
                int m = wm * 32 + fb * 8 + (lane & 3) * 2;
                S[n * 132 + m]           = acc[nb][fb][0];
                S[n * 132 + m + 1]       = acc[nb][fb][1];
                S[(n + 8) * 132 + m]     = acc[nb][fb][2];
                S[(n + 8) * 132 + m + 1] = acc[nb][fb][3];
            }
    }
    __syncthreads();

    float* slab = g_S + (size_t)kh * SLAB;
#pragma unroll
    for (int it = 0; it < 4; it++) {
        int v = tid + it * 512, n = v >> 5, m4 = (v & 31) << 2;
        float4 val = *(const float4*)&S[n * 132 + m4];
        *(float4*)(slab + ((size_t)n * Cc + c) * Cc + m4) = val;
    }
}

// ---------------------------------------------------------------------------
// Softmax: combine the two K-slabs, softmax over m, emit bf16 hi/lo weights.
// ---------------------------------------------------------------------------
__global__ __launch_bounds__(256) void k_softmax() {
    const int tid = threadIdx.x, wid = tid >> 5, lane = tid & 31;
    const int r0 = blockIdx.x * 32 + wid * 4;
#pragma unroll
    for (int j = 0; j < 4; j++) {
        int r = r0 + j;
        size_t base = (size_t)r * Cc;
        float v0 = g_S[base + lane]      + g_S[SLAB + base + lane];
        float v1 = g_S[base + lane + 32] + g_S[SLAB + base + lane + 32];
        float v2 = g_S[base + lane + 64] + g_S[SLAB + base + lane + 64];
        float v3 = g_S[base + lane + 96] + g_S[SLAB + base + lane + 96];
        float mx = fmaxf(fmaxf(v0, v1), fmaxf(v2, v3));
#pragma unroll
        for (int o = 16; o > 0; o >>= 1)
            mx = fmaxf(mx, __shfl_xor_sync(0xffffffffu, mx, o));
        float e0 = __expf(v0 - mx);
        float e1 = __expf(v1 - mx);
        float e2 = __expf(v2 - mx);
        float e3 = __expf(v3 - mx);
        float s = e0 + e1 + e2 + e3;
#pragma unroll
        for (int o = 16; o > 0; o >>= 1)
            s += __shfl_xor_sync(0xffffffffu, s, o);
        float inv = 1.0f / s;
        float w[4] = {e0 * inv, e1 * inv, e2 * inv, e3 * inv};
#pragma unroll
        for (int q = 0; q < 4; q++) {
            __nv_bfloat16 h = __float2bfloat16(w[q]);
            __nv_bfloat16 l = __float2bfloat16(w[q] - __bfloat162float(h));
            g_Wh[base + lane + q * 32] = h;
            g_Wl[base + lane + q * 32] = l;
        }
    }
}

// ---------------------------------------------------------------------------
// Kernel 2: per (n, f-tile 64), 512 threads, 2 CTAs/SM:
// out[c=128][f=64] = sum_m W[n,c,m]*X[n,m,f]. K = m = 128 resident.
// W streamed in via cp.async (pre-split bf16, pure 16B copies, overlapped
// with X fp32->bf16 hi/lo conversion); B frags via ldmatrix.trans.
// Warp tile: c 4x32 (wm), f 4x16 (wf). Full 3-product split.
// ---------------------------------------------------------------------------
#define K2_SW 136
#define K2_ST 72
#define K2_WH 0
#define K2_WL 34816
#define K2_TH 69632
#define K2_TL 88064
#define K2_DYN 106496

__global__ __launch_bounds__(512, 2) void k_combine(const float* __restrict__ X,
                                                    float* __restrict__ out) {
    extern __shared__ char sm[];
    const uint32_t sbase = smem_u32(sm);
    const int n = blockIdx.y, fblk = blockIdx.x * 64;
    const int tid = threadIdx.x;
    const int wid = tid >> 5, lane = tid & 31;
    const int wm = wid >> 2, wf = wid & 3;  // c0 = wm*32, f0 = wf*16

    __nv_bfloat16* Th = (__nv_bfloat16*)(sm + K2_TH);
    __nv_bfloat16* Tl = (__nv_bfloat16*)(sm + K2_TL);

    const uint32_t wh = sbase + K2_WH, wl = sbase + K2_WL;
    const uint32_t th = sbase + K2_TH, tl = sbase + K2_TL;

    // W[n]: pre-split bf16 -> async 16B copies into stride-136 rows.
    // 128 rows x 16 segs x {hi,lo} = 4096 ops, 8 per thread.
    const __nv_bfloat16* WhG = g_Wh + (size_t)n * Cc * Cc;
    const __nv_bfloat16* WlG = g_Wl + (size_t)n * Cc * Cc;
#pragma unroll
    for (int it = 0; it < 8; it++) {
        int v   = tid + it * 512;
        int seg = v & 15, row = (v >> 4) & 127, hl = v >> 11;
        const __nv_bfloat16* src = (hl ? WlG : WhG) + row * Cc + seg * 8;
        uint32_t dst = (hl ? wl : wh) + (uint32_t)(row * K2_SW + seg * 8) * 2;
        cp_async16(dst, src);
    }
    CP_COMMIT();

    // X[n]: [m][f-tile 64] fp32 -> Th/Tl natural [m][f] stride 72 (overlaps W)
    const float* Xb = X + (size_t)n * Cc * Ff + fblk;
#pragma unroll
    for (int it = 0; it < 4; it++) {
        int v = tid + it * 512, m = v >> 4, f4 = (v & 15) << 2;
        float4 x = *(const float4*)(Xb + (size_t)m * Ff + f4);
        uint32_t h01, l01, h23, l23;
        split2(x.x, x.y, h01, l01);
        split2(x.z, x.w, h23, l23);
        int e = m * K2_ST + f4;
        *(uint2*)(Th + e) = make_uint2(h01, h23);
        *(uint2*)(Tl + e) = make_uint2(l01, l23);
    }
    CP_WAIT0();
    __syncthreads();

    float acc[2][2][4];
#pragma unroll
    for (int nb = 0; nb < 2; nb++)
#pragma unroll
        for (int fb = 0; fb < 2; fb++)
#pragma unroll
            for (int j = 0; j < 4; j++) acc[nb][fb][j] = 0.0f;

#pragma unroll
    for (int ks = 0; ks < 8; ks++) {
        uint32_t wah[2][4], wal[2][4];
#pragma unroll
        for (int nb = 0; nb < 2; nb++) {
            int row  = wm * 32 + nb * 16 + (lane & 15);
            int koff = ks * 16 + ((lane >> 4) << 3);
            uint32_t off = (uint32_t)(row * K2_SW + koff) * 2;
            ldm4(wah[nb], wh + off);
            ldm4(wal[nb], wl + off);
        }
        uint32_t bhf[4], blf[4];
        {
            int kr = ks * 16 + (((lane >> 3) & 1) << 3) + (lane & 7);
            int nc = wf * 16 + ((lane >> 4) << 3);
            uint32_t off = (uint32_t)(kr * K2_ST + nc) * 2;
            ldm4t(bhf, th + off);
            ldm4t(blf, tl + off);
        }
#pragma unroll
        for (int nb = 0; nb < 2; nb++)
#pragma unroll
            for (int h = 0; h < 2; h++) {
                mma_bf16(acc[nb][h], wah[nb], &bhf[h * 2]);
                mma_bf16(acc[nb][h], wah[nb], &blf[h * 2]);
                mma_bf16(acc[nb][h], wal[nb], &bhf[h * 2]);
            }
    }
    __syncthreads();  // tiles done; reuse smem

    float* S = (float*)sm;  // [c=128][f 64 pad 68]
#pragma unroll
    for (int nb = 0; nb < 2; nb++)
#pragma unroll
        for (int fb = 0; fb < 2; fb++) {
            int cc = wm * 32 + nb * 16 + (lane >> 2);
            int f  = wf * 16 + fb * 8 + (lane & 3) * 2;
            *(float2*)&S[cc * 68 + f]       = make_float2(acc[nb][fb][0], acc[nb][fb][1]);
            *(float2*)&S[(cc + 8) * 68 + f] = make_float2(acc[nb][fb][2], acc[nb][fb][3]);
        }
    __syncthreads();

#pragma unroll
    for (int it = 0; it < 4; it++) {
        int v = tid + it * 512, row = v >> 4, f4 = (v & 15) << 2;
        float4 val = *(const float4*)&S[row * 68 + f4];
        *(float4*)(out + ((size_t)n * Cc + row) * Ff + fblk + f4) = val;
    }
}

extern "C" void kernel_launch(void* const* d_in, const int* in_sizes, int n_in,
                              void* d_out, int out_size) {
    const float* X = (const float*)d_in[0];
    const float* A = (const float*)d_in[1];
    float* out = (float*)d_out;
    (void)in_sizes; (void)n_in; (void)out_size;

    cudaFuncSetAttribute(k_scores, cudaFuncAttributeMaxDynamicSharedMemorySize, K1_DYN);
    cudaFuncSetAttribute(k_combine, cudaFuncAttributeMaxDynamicSharedMemorySize, K2_DYN);

    k_scores<<<dim3(128, 2), 512, K1_DYN>>>(X, A);
    k_softmax<<<256, 256>>>();
    k_combine<<<dim3(32, 64), 512, K2_DYN>>>(X, out);
}